// round 2
// baseline (speedup 1.0000x reference)
#include <cuda_runtime.h>

#define BB   32
#define EE   48
#define MM   96
#define DD   256
#define HH   8
#define DPH  32
#define PAIRS (EE*EE)
#define MAXML 64

// ---------------- scratch (no allocation allowed -> device globals) ----------------
__device__ int   g_is32;
__device__ int   g_sidx[BB*MM];
__device__ int   g_mid [BB*MM];
__device__ int   g_mlist[BB*EE*MAXML];
__device__ int   g_mcnt [BB*EE];
__device__ float g_qp [2][BB*EE*DD];          // projected queries per weight-set
__device__ float g_kp [2][BB*MM*DD];          // projected keys (from gathered sentences)
__device__ float g_v  [2][BB*MM*DD];          // projected values
__device__ float g_voh[2][BB*MM*HH*DD];       // per-head value projected through Wout
__device__ float g_sc [2][BB*EE*HH*MM];       // scores [b][jq][h][m]

// ---------------- dtype detection for info (int32 vs int64) ----------------
__global__ void k_detect(const void* info) {
    const int* p = (const int*)info;
    int t = threadIdx.x;
    int mx = 0;
    for (int r = t; r < BB*MM; r += 256) mx = max(mx, p[r*6 + 4]);
    __shared__ int s[256];
    s[t] = mx; __syncthreads();
    for (int o = 128; o > 0; o >>= 1) { if (t < o) s[t] = max(s[t], s[t+o]); __syncthreads(); }
    if (t == 0) g_is32 = (s[0] > 0) ? 1 : 0;   // int64 layout reads always-zero slots here
}

__global__ void k_extract(const void* info) {
    int r = blockIdx.x * blockDim.x + threadIdx.x;
    if (r >= BB*MM) return;
    int e, sidx;
    if (g_is32) {
        const int* p = (const int*)info;
        e = p[r*6 + 0]; sidx = p[r*6 + 4];
    } else {
        const long long* p = (const long long*)info;
        e = (int)p[r*6 + 0]; sidx = (int)p[r*6 + 4];
    }
    g_mid[r] = e; g_sidx[r] = sidx;
}

__global__ void k_lists() {
    int b = blockIdx.x;
    int e = threadIdx.x;
    if (e >= EE) return;
    int target = b*EE + e;
    int cnt = 0;
    for (int m = 0; m < MM; m++) {
        if (g_mid[b*MM + m] == target && cnt < MAXML)
            g_mlist[(b*EE + e)*MAXML + cnt++] = m;
    }
    g_mcnt[b*EE + e] = cnt;
}

// ---------------- projection GEMM: C[rows,256] = A[rows,256] @ W + bias ----------------
// dst selector: 0/1 qp, 2/3 kp, 4/5 v
__global__ void k_proj(const float* __restrict__ A, const float* __restrict__ W,
                       const float* __restrict__ bias, int use_gather, int dst) {
    __shared__ float As[32][33];
    __shared__ float Ws[32][DD];
    int tid = threadIdx.x;
    int r0  = blockIdx.x * 32;

    float acc[32];
#pragma unroll
    for (int r = 0; r < 32; r++) acc[r] = 0.f;

    for (int k0 = 0; k0 < DD; k0 += 32) {
#pragma unroll
        for (int j = 0; j < 32; j++) Ws[j][tid] = W[(k0 + j)*DD + tid];
#pragma unroll
        for (int j = 0; j < 4; j++) {
            int i  = tid + j*256;
            int r  = i >> 5, kk = i & 31;
            int row = r0 + r;
            int src = use_gather ? g_sidx[row] : row;
            As[r][kk] = A[src*DD + k0 + kk];
        }
        __syncthreads();
#pragma unroll
        for (int kk = 0; kk < 32; kk++) {
            float w = Ws[kk][tid];
#pragma unroll
            for (int r = 0; r < 32; r++) acc[r] += As[r][kk] * w;
        }
        __syncthreads();
    }

    float* C;
    switch (dst) {
        case 0: C = g_qp[0]; break;
        case 1: C = g_qp[1]; break;
        case 2: C = g_kp[0]; break;
        case 3: C = g_kp[1]; break;
        case 4: C = g_v[0];  break;
        default: C = g_v[1]; break;
    }
    float bv = bias[tid];
#pragma unroll
    for (int r = 0; r < 32; r++) C[(r0 + r)*DD + tid] = acc[r] + bv;
}

// ---------------- per-head value->output projection: voh[b,m,h,:] = v[b,m,h*32:+32] @ Wout[h*32:+32,:] ----------------
__global__ void k_voh(const float* __restrict__ W1, const float* __restrict__ W2) {
    int b = blockIdx.x, set = blockIdx.y, h = blockIdx.z;
    const float* Wout = (set == 0 ? W1 : W2) + 3*DD*DD;
    __shared__ float Wh[DPH][DD];   // 32 KB
    __shared__ float vs[MM][DPH];   // 12 KB
    int tid = threadIdx.x;

#pragma unroll
    for (int j = 0; j < DPH; j++) Wh[j][tid] = Wout[(h*DPH + j)*DD + tid];
    for (int i = tid; i < MM*DPH; i += 256) {
        int m = i >> 5, d = i & 31;
        vs[m][d] = g_v[set][(b*MM + m)*DD + h*DPH + d];
    }
    __syncthreads();

    for (int m = 0; m < MM; m++) {
        float acc = 0.f;
#pragma unroll
        for (int d = 0; d < DPH; d++) acc += vs[m][d] * Wh[d][tid];
        g_voh[set][((b*MM + m)*HH + h)*DD + tid] = acc;
    }
}

// ---------------- scores: s[b][jq][h][m] = (q . k) / sqrt(32) ----------------
__global__ void k_scores() {
    int h = blockIdx.x, b = blockIdx.y, set = blockIdx.z;
    __shared__ float qh[EE][DPH + 1];
    __shared__ float kh[MM][DPH + 1];
    int tid = threadIdx.x;

    for (int i = tid; i < EE*DPH; i += 256) {
        int j = i >> 5, d = i & 31;
        qh[j][d] = g_qp[set][(b*EE + j)*DD + h*DPH + d];
    }
    for (int i = tid; i < MM*DPH; i += 256) {
        int m = i >> 5, d = i & 31;
        kh[m][d] = g_kp[set][(b*MM + m)*DD + h*DPH + d];
    }
    __syncthreads();

    const float scale = 0.17677669529663687f;  // 1/sqrt(32)
    for (int idx = tid; idx < EE*MM; idx += 256) {
        int j = idx / MM, m = idx % MM;
        float acc = 0.f;
#pragma unroll
        for (int d = 0; d < DPH; d++) acc += qh[j][d] * kh[m][d];
        g_sc[set][((b*EE + j)*HH + h)*MM + m] = acc * scale;
    }
}

// ---------------- combine: masked softmax + (alpha . voh) + bias + residual + LayerNorm ----------------
__global__ void k_combine(const float* __restrict__ ent,
                          const float* __restrict__ b1, const float* __restrict__ ln1,
                          const float* __restrict__ b2, const float* __restrict__ ln2,
                          float* __restrict__ out) {
    int e = blockIdx.x, b = blockIdx.y, set = blockIdx.z;
    int tid = threadIdx.x;

    const float* bb = (set == 0 ? b1 : b2) + 3*DD;
    const float* ln = (set == 0 ? ln1 : ln2);
    float bo  = bb[tid];
    float gma = ln[tid];
    float bta = ln[DD + tid];

    int cnt = g_mcnt[b*EE + e];

    __shared__ int   ml[MAXML];
    __shared__ float alpha[HH][MAXML];
    __shared__ float red[8];

    if (tid < cnt) ml[tid] = g_mlist[(b*EE + e)*MAXML + tid];
    __syncthreads();

    for (int q = 0; q < EE; q++) {
        // --- softmax over this entity's mention set, one head per thread 0..7 ---
        if (tid < HH) {
            int h = tid;
            const float* sp = &g_sc[set][((b*EE + q)*HH + h)*MM];
            float mx = -1e30f;
            for (int i = 0; i < cnt; i++) mx = fmaxf(mx, sp[ml[i]]);
            float s = 0.f;
            for (int i = 0; i < cnt; i++) {
                float ev = __expf(sp[ml[i]] - mx);
                alpha[h][i] = ev; s += ev;
            }
            float inv = 1.f / s;
            for (int i = 0; i < cnt; i++) alpha[h][i] *= inv;
        }
        __syncthreads();

        // --- out[c] = b_out[c] + sum_{m,h} alpha[h][m] * voh[b,m,h,c] ---
        float acc = bo;
        for (int i = 0; i < cnt; i++) {
            const float* vp = &g_voh[set][((size_t)(b*MM + ml[i])*HH)*DD + tid];
#pragma unroll
            for (int h = 0; h < HH; h++) acc += alpha[h][i] * vp[h*DD];
        }

        float resid = ent[(b*EE + q)*DD + tid];
        float x = acc + resid;

        // --- LayerNorm over 256 ---
        float sm = x;
#pragma unroll
        for (int o = 16; o > 0; o >>= 1) sm += __shfl_xor_sync(0xffffffffu, sm, o);
        if ((tid & 31) == 0) red[tid >> 5] = sm;
        __syncthreads();
        float tot = 0.f;
#pragma unroll
        for (int w = 0; w < 8; w++) tot += red[w];
        float mu = tot * (1.f / DD);
        float d  = x - mu;

        float dv = d * d;
#pragma unroll
        for (int o = 16; o > 0; o >>= 1) dv += __shfl_xor_sync(0xffffffffu, dv, o);
        __syncthreads();                 // red read above must finish before rewrite
        if ((tid & 31) == 0) red[tid >> 5] = dv;
        __syncthreads();
        float var = 0.f;
#pragma unroll
        for (int w = 0; w < 8; w++) var += red[w];
        var *= (1.f / DD);

        float y = d * rsqrtf(var + 1e-5f) * gma + bta;

        int orow = (set == 0) ? (e*EE + q) : (q*EE + e);
        size_t off = ((size_t)set * BB * PAIRS + (size_t)b * PAIRS + orow) * DD + tid;
        out[off] = y;
        __syncthreads();                 // alpha/red rewritten next q
    }
}

// ---------------- launch ----------------
extern "C" void kernel_launch(void* const* d_in, const int* in_sizes, int n_in,
                              void* d_out, int out_size) {
    const void*  info = d_in[0];
    // d_in[1] = section (unused)
    const float* ent  = (const float*)d_in[2];
    const float* men  = (const float*)d_in[3];
    const float* sen  = (const float*)d_in[4];
    const float* W1   = (const float*)d_in[5];
    const float* b1   = (const float*)d_in[6];
    const float* ln1  = (const float*)d_in[7];
    const float* W2   = (const float*)d_in[8];
    const float* b2   = (const float*)d_in[9];
    const float* ln2  = (const float*)d_in[10];
    float* out = (float*)d_out;

    k_detect <<<1, 256>>>(info);
    k_extract<<<(BB*MM + 255)/256, 256>>>(info);
    k_lists  <<<BB, 64>>>();

    // projections: q (entities), k (gathered sentences), v (mentions), both weight sets
    k_proj<<<BB*EE/32, 256>>>(ent, W1 + 0*DD*DD, b1 + 0*DD, 0, 0);
    k_proj<<<BB*EE/32, 256>>>(ent, W2 + 0*DD*DD, b2 + 0*DD, 0, 1);
    k_proj<<<BB*MM/32, 256>>>(sen, W1 + 1*DD*DD, b1 + 1*DD, 1, 2);
    k_proj<<<BB*MM/32, 256>>>(sen, W2 + 1*DD*DD, b2 + 1*DD, 1, 3);
    k_proj<<<BB*MM/32, 256>>>(men, W1 + 2*DD*DD, b1 + 2*DD, 0, 4);
    k_proj<<<BB*MM/32, 256>>>(men, W2 + 2*DD*DD, b2 + 2*DD, 0, 5);

    k_voh<<<dim3(BB, 2, HH), 256>>>(W1, W2);
    k_scores<<<dim3(HH, BB, 2), 256>>>();
    k_combine<<<dim3(EE, BB, 2), 256>>>(ent, b1, ln1, b2, ln2, out);
}

// round 3
// speedup vs baseline: 2.1522x; 2.1522x over previous
#include <cuda_runtime.h>

#define BB   32
#define EE   48
#define MM   96
#define DD   256
#define HH   8
#define DPH  32
#define PAIRS (EE*EE)
#define MAXML 64
#define IC   4

// ---------------- scratch (no allocation allowed -> device globals) ----------------
__device__ int   g_is32;
__device__ int   g_sidx[BB*MM];
__device__ int   g_mid [BB*MM];
__device__ int   g_mlist[BB*EE*MAXML];
__device__ int   g_mcnt [BB*EE];
__device__ float g_qp [2][BB*EE*DD];
__device__ float g_kp [2][BB*MM*DD];
__device__ float g_v  [2][BB*MM*DD];
__device__ float g_voh[2][BB*MM*HH*DD];
__device__ float g_sc [2][BB*EE*HH*MM];

// ---------------- dtype detection for info (int32 vs int64) ----------------
__global__ void k_detect(const void* info) {
    const int* p = (const int*)info;
    int t = threadIdx.x;
    int mx = 0;
    for (int r = t; r < BB*MM; r += 256) mx = max(mx, p[r*6 + 4]);
    __shared__ int s[256];
    s[t] = mx; __syncthreads();
    for (int o = 128; o > 0; o >>= 1) { if (t < o) s[t] = max(s[t], s[t+o]); __syncthreads(); }
    if (t == 0) g_is32 = (s[0] > 0) ? 1 : 0;
}

__global__ void k_extract(const void* info) {
    int r = blockIdx.x * blockDim.x + threadIdx.x;
    if (r >= BB*MM) return;
    int e, sidx;
    if (g_is32) {
        const int* p = (const int*)info;
        e = p[r*6 + 0]; sidx = p[r*6 + 4];
    } else {
        const long long* p = (const long long*)info;
        e = (int)p[r*6 + 0]; sidx = (int)p[r*6 + 4];
    }
    g_mid[r] = e; g_sidx[r] = sidx;
}

__global__ void k_lists() {
    int b = blockIdx.x;
    int e = threadIdx.x;
    if (e >= EE) return;
    int target = b*EE + e;
    int cnt = 0;
    for (int m = 0; m < MM; m++) {
        if (g_mid[b*MM + m] == target && cnt < MAXML)
            g_mlist[(b*EE + e)*MAXML + cnt++] = m;
    }
    g_mcnt[b*EE + e] = cnt;
}

// ---------------- all 6 projections in ONE launch: 128x128 tiled SGEMM ----------------
// rows per set: q 1536 (12 tiles), k 3072 (24), v 3072 (24) -> 60 row-tiles/set, 120 total
// grid.x = 120 * 2 col-tiles = 240
__global__ __launch_bounds__(256) void k_proj_all(
    const float* __restrict__ ent, const float* __restrict__ men, const float* __restrict__ sen,
    const float* __restrict__ W1, const float* __restrict__ b1,
    const float* __restrict__ W2, const float* __restrict__ b2)
{
    __shared__ float As[8][128];
    __shared__ float Ws[8][128];

    int blk = blockIdx.x;
    int cb = blk & 1, rb = blk >> 1;
    int set = rb / 60; int r = rb % 60;
    const float* A; int gather = 0, type, row0;
    if (r < 12)      { type = 0; row0 = r*128;      A = ent; }
    else if (r < 36) { type = 1; row0 = (r-12)*128; A = sen; gather = 1; }
    else             { type = 2; row0 = (r-36)*128; A = men; }
    const float* W  = (set ? W2 : W1) + type*DD*DD;
    const float* bi = (set ? b2 : b1) + type*DD;
    float* C = (type == 0) ? g_qp[set] : (type == 1 ? g_kp[set] : g_v[set]);
    int n0 = cb*128;

    int tid = threadIdx.x;
    int tx = tid & 15, ty = tid >> 4;

    // A-tile loader: thread -> (row am, k-quad akq)
    int am  = tid >> 1;
    int akq = (tid & 1) * 4;
    int arow = row0 + am;
    int asrc = gather ? g_sidx[arow] : arow;
    const float* aptr = A + (size_t)asrc*DD + akq;
    // W-tile loader: thread -> (k row wk, n-quad wn)
    int wk = tid >> 5;
    int wn = (tid & 31) * 4;
    const float* wptr = W + (size_t)wk*DD + n0 + wn;

    float acc[8][8];
#pragma unroll
    for (int i = 0; i < 8; i++)
#pragma unroll
        for (int j = 0; j < 8; j++) acc[i][j] = 0.f;

    for (int k0 = 0; k0 < DD; k0 += 8) {
        float4 av = *(const float4*)(aptr + k0);
        float4 wv = *(const float4*)(wptr + (size_t)k0*DD);
        As[akq+0][am] = av.x; As[akq+1][am] = av.y;
        As[akq+2][am] = av.z; As[akq+3][am] = av.w;
        *(float4*)&Ws[wk][wn] = wv;
        __syncthreads();
#pragma unroll
        for (int kk = 0; kk < 8; kk++) {
            float4 a0 = *(float4*)&As[kk][ty*8];
            float4 a1 = *(float4*)&As[kk][ty*8 + 4];
            float4 b0 = *(float4*)&Ws[kk][tx*8];
            float4 b1v = *(float4*)&Ws[kk][tx*8 + 4];
            float a[8] = {a0.x,a0.y,a0.z,a0.w,a1.x,a1.y,a1.z,a1.w};
            float bfr[8] = {b0.x,b0.y,b0.z,b0.w,b1v.x,b1v.y,b1v.z,b1v.w};
#pragma unroll
            for (int i = 0; i < 8; i++)
#pragma unroll
                for (int j = 0; j < 8; j++) acc[i][j] += a[i] * bfr[j];
        }
        __syncthreads();
    }

    float bj[8];
#pragma unroll
    for (int j = 0; j < 8; j++) bj[j] = bi[n0 + tx*8 + j];
#pragma unroll
    for (int i = 0; i < 8; i++) {
        int row = row0 + ty*8 + i;
        float* crow = C + (size_t)row*DD + n0 + tx*8;
        float4 o0, o1;
        o0.x = acc[i][0]+bj[0]; o0.y = acc[i][1]+bj[1];
        o0.z = acc[i][2]+bj[2]; o0.w = acc[i][3]+bj[3];
        o1.x = acc[i][4]+bj[4]; o1.y = acc[i][5]+bj[5];
        o1.z = acc[i][6]+bj[6]; o1.w = acc[i][7]+bj[7];
        *(float4*)crow       = o0;
        *(float4*)(crow + 4) = o1;
    }
}

// ---------------- per-head value->output projection ----------------
__global__ void k_voh(const float* __restrict__ W1, const float* __restrict__ W2) {
    int b = blockIdx.x, set = blockIdx.y, h = blockIdx.z;
    const float* Wout = (set == 0 ? W1 : W2) + 3*DD*DD;
    __shared__ float Wh[DPH][DD];
    __shared__ float vs[MM][DPH];
    int tid = threadIdx.x;

#pragma unroll
    for (int j = 0; j < DPH; j++) Wh[j][tid] = Wout[(h*DPH + j)*DD + tid];
    for (int i = tid; i < MM*DPH; i += 256) {
        int m = i >> 5, d = i & 31;
        vs[m][d] = g_v[set][(b*MM + m)*DD + h*DPH + d];
    }
    __syncthreads();

    for (int m = 0; m < MM; m++) {
        float acc = 0.f;
#pragma unroll
        for (int d = 0; d < DPH; d++) acc += vs[m][d] * Wh[d][tid];
        g_voh[set][((size_t)(b*MM + m)*HH + h)*DD + tid] = acc;
    }
}

// ---------------- scores ----------------
__global__ void k_scores() {
    int h = blockIdx.x, b = blockIdx.y, set = blockIdx.z;
    __shared__ float qh[EE][DPH + 1];
    __shared__ float kh[MM][DPH + 1];
    int tid = threadIdx.x;

    for (int i = tid; i < EE*DPH; i += 256) {
        int j = i >> 5, d = i & 31;
        qh[j][d] = g_qp[set][(b*EE + j)*DD + h*DPH + d];
    }
    for (int i = tid; i < MM*DPH; i += 256) {
        int m = i >> 5, d = i & 31;
        kh[m][d] = g_kp[set][(b*MM + m)*DD + h*DPH + d];
    }
    __syncthreads();

    const float scale = 0.17677669529663687f;
    for (int idx = tid; idx < EE*MM; idx += 256) {
        int j = idx / MM, m = idx % MM;
        float acc = 0.f;
#pragma unroll
        for (int d = 0; d < DPH; d++) acc += qh[j][d] * kh[m][d];
        g_sc[set][((b*EE + j)*HH + h)*MM + m] = acc * scale;
    }
}

// ---------------- combine v2: warp-per-row, shared V tile, shuffle LayerNorm ----------------
__global__ __launch_bounds__(256) void k_combine(
    const float* __restrict__ ent,
    const float* __restrict__ b1, const float* __restrict__ ln1,
    const float* __restrict__ b2, const float* __restrict__ ln2,
    float* __restrict__ out)
{
    int e = blockIdx.x, b = blockIdx.y, set = blockIdx.z;
    int tid = threadIdx.x, lane = tid & 31, wid = tid >> 5;

    __shared__ int   ml[MAXML];
    __shared__ float mxs[EE*HH];
    __shared__ float ise[EE*HH];
    __shared__ float alpha_s[EE*HH*IC];
    __shared__ float Vs[IC*HH][DD];

    int cnt = g_mcnt[b*EE + e];
    if (tid < MAXML) ml[tid] = (tid < cnt) ? g_mlist[(b*EE + e)*MAXML + tid] : 0;
    __syncthreads();

    const float* scb = g_sc[set] + (size_t)b*EE*HH*MM;

    // stage A: per (q,h) softmax max + inverse sum (384 tasks over 256 threads)
    for (int t = tid; t < EE*HH; t += 256) {
        const float* sp = scb + t*MM;      // t = q*HH + h matches layout
        float mx = -1e30f;
        for (int i = 0; i < cnt; i++) mx = fmaxf(mx, sp[ml[i]]);
        float s = 0.f;
        for (int i = 0; i < cnt; i++) s += __expf(sp[ml[i]] - mx);
        mxs[t] = mx; ise[t] = 1.f / s;
    }

    // per-thread d-slice constants (d = lane + 32*j)
    const float* bb = (set ? b2 : b1) + 3*DD;
    const float* ln = (set ? ln2 : ln1);
    float bo[8], gm[8], bt[8];
#pragma unroll
    for (int j = 0; j < 8; j++) {
        int d = lane + 32*j;
        bo[j] = bb[d]; gm[j] = ln[d]; bt[j] = ln[DD + d];
    }

    float acc[6][8];
#pragma unroll
    for (int t = 0; t < 6; t++)
#pragma unroll
        for (int j = 0; j < 8; j++) acc[t][j] = 0.f;

    __syncthreads();   // mxs/ise ready

    for (int ic0 = 0; ic0 < cnt; ic0 += IC) {
        int icn = min(IC, cnt - ic0);
        int rows = icn * HH;
        // stage the mention value-rows into shared (read from L2 ONCE per block)
        for (int idx = tid; idx < rows*DD; idx += 256) {
            int rr = idx >> 8, d = idx & 255;
            int ii = rr >> 3, h = rr & 7;
            int m = ml[ic0 + ii];
            Vs[rr][d] = g_voh[set][(((size_t)(b*MM + m))*HH + h)*DD + d];
        }
        // normalized alphas for this chunk
        for (int t = tid; t < EE*HH*icn; t += 256) {
            int qh = t / icn, ii = t - qh*icn;
            float sv = scb[qh*MM + ml[ic0 + ii]];
            alpha_s[qh*IC + ii] = __expf(sv - mxs[qh]) * ise[qh];
        }
        __syncthreads();
        // accumulate: warp w owns q = w, w+8, ..., w+40
#pragma unroll
        for (int t = 0; t < 6; t++) {
            int q = wid + 8*t;
            for (int p = 0; p < rows; p++) {
                int ii = p >> 3, h = p & 7;
                float a = alpha_s[(q*HH + h)*IC + ii];
#pragma unroll
                for (int j = 0; j < 8; j++) acc[t][j] += a * Vs[p][lane + 32*j];
            }
        }
        __syncthreads();
    }

    // epilogue: bias + residual + LayerNorm (warp shuffles only)
#pragma unroll
    for (int t = 0; t < 6; t++) {
        int q = wid + 8*t;
        const float* er = ent + (size_t)(b*EE + q)*DD;
        float x[8]; float sm = 0.f;
#pragma unroll
        for (int j = 0; j < 8; j++) {
            x[j] = acc[t][j] + bo[j] + er[lane + 32*j];
            sm += x[j];
        }
#pragma unroll
        for (int o = 16; o > 0; o >>= 1) sm += __shfl_xor_sync(0xffffffffu, sm, o);
        float mu = sm * (1.f/DD);
        float vv = 0.f;
#pragma unroll
        for (int j = 0; j < 8; j++) { x[j] -= mu; vv += x[j]*x[j]; }
#pragma unroll
        for (int o = 16; o > 0; o >>= 1) vv += __shfl_xor_sync(0xffffffffu, vv, o);
        float rs = rsqrtf(vv*(1.f/DD) + 1e-5f);

        int orow = set ? (q*EE + e) : (e*EE + q);
        float* op = out + ((size_t)set*BB*PAIRS + (size_t)b*PAIRS + orow)*DD;
#pragma unroll
        for (int j = 0; j < 8; j++) op[lane + 32*j] = x[j]*rs*gm[j] + bt[j];
    }
}

// ---------------- launch ----------------
extern "C" void kernel_launch(void* const* d_in, const int* in_sizes, int n_in,
                              void* d_out, int out_size) {
    const void*  info = d_in[0];
    const float* ent  = (const float*)d_in[2];
    const float* men  = (const float*)d_in[3];
    const float* sen  = (const float*)d_in[4];
    const float* W1   = (const float*)d_in[5];
    const float* b1   = (const float*)d_in[6];
    const float* ln1  = (const float*)d_in[7];
    const float* W2   = (const float*)d_in[8];
    const float* b2   = (const float*)d_in[9];
    const float* ln2  = (const float*)d_in[10];
    float* out = (float*)d_out;

    k_detect <<<1, 256>>>(info);
    k_extract<<<(BB*MM + 255)/256, 256>>>(info);
    k_lists  <<<BB, 64>>>();

    k_proj_all<<<240, 256>>>(ent, men, sen, W1, b1, W2, b2);
    k_voh   <<<dim3(BB, 2, HH), 256>>>(W1, W2);
    k_scores<<<dim3(HH, BB, 2), 256>>>();
    k_combine<<<dim3(EE, BB, 2), 256>>>(ent, b1, ln1, b2, ln2, out);
}

// round 4
// speedup vs baseline: 2.4145x; 1.1219x over previous
#include <cuda_runtime.h>

#define BB   32
#define EE   48
#define MM   96
#define DD   256
#define HH   8
#define DPH  32
#define PAIRS (EE*EE)
#define MAXML 64
#define IC   4

// ---------------- scratch ----------------
__device__ int   g_sidx[BB*MM];
__device__ int   g_mid [BB*MM];
__device__ int   g_mlist[BB*EE*MAXML];
__device__ int   g_mcnt [BB*EE];
__device__ float g_qp [2][BB*EE*DD];
__device__ float g_kp [2][BB*MM*DD];
__device__ float g_v  [2][BB*MM*DD];
__device__ float g_voh[2][BB*MM*HH*DD];
__device__ float g_sc [2][BB*EE*HH*MM];

// packed f32x2 FMA: d = a*b + d (lane-wise on packed pairs)
__device__ __forceinline__ void fma2(float2& d, float2 a, float2 b) {
    unsigned long long dd = *(unsigned long long*)&d;
    unsigned long long aa = *(unsigned long long*)&a;
    unsigned long long bb = *(unsigned long long*)&b;
    asm("fma.rn.f32x2 %0, %1, %2, %0;" : "+l"(dd) : "l"(aa), "l"(bb));
    d = *(float2*)&dd;
}

// ---------------- prep: dtype detect + extract + mention lists (1 block) ----------------
__global__ void k_prep(const void* info) {
    int tid = threadIdx.x;
    __shared__ int s[256];
    // detect int32 vs int64 layout of info
    const int* p32 = (const int*)info;
    int mx = 0;
    for (int r = tid; r < BB*MM; r += 256) mx = max(mx, p32[r*6 + 4]);
    s[tid] = mx; __syncthreads();
    for (int o = 128; o > 0; o >>= 1) { if (tid < o) s[tid] = max(s[tid], s[tid+o]); __syncthreads(); }
    int is32 = (s[0] > 0);
    // extract entity id + sentence idx
    for (int r = tid; r < BB*MM; r += 256) {
        int e, sidx;
        if (is32) { e = p32[r*6 + 0]; sidx = p32[r*6 + 4]; }
        else {
            const long long* p64 = (const long long*)info;
            e = (int)p64[r*6 + 0]; sidx = (int)p64[r*6 + 4];
        }
        g_mid[r] = e; g_sidx[r] = sidx;
    }
    __syncthreads();
    // per-entity mention lists
    for (int t = tid; t < BB*EE; t += 256) {
        int b = t / EE;
        int cnt = 0;
        for (int m = 0; m < MM; m++) {
            if (g_mid[b*MM + m] == t && cnt < MAXML)
                g_mlist[t*MAXML + cnt++] = m;
        }
        g_mcnt[t] = cnt;
    }
}

// ---------------- all 6 projections: 128x128 tiles, f32x2 inner ----------------
__global__ __launch_bounds__(256) void k_proj_all(
    const float* __restrict__ ent, const float* __restrict__ men, const float* __restrict__ sen,
    const float* __restrict__ W1, const float* __restrict__ b1,
    const float* __restrict__ W2, const float* __restrict__ b2)
{
    __shared__ float2 As2[8][128];   // duplicated {a,a}
    __shared__ float2 Ws2[8][64];    // natural col pairs

    int blk = blockIdx.x;
    int cb = blk & 1, rb = blk >> 1;
    int set = rb / 60; int r = rb % 60;
    const float* A; int gather = 0, type, row0;
    if (r < 12)      { type = 0; row0 = r*128;      A = ent; }
    else if (r < 36) { type = 1; row0 = (r-12)*128; A = sen; gather = 1; }
    else             { type = 2; row0 = (r-36)*128; A = men; }
    const float* W  = (set ? W2 : W1) + type*DD*DD;
    const float* bi = (set ? b2 : b1) + type*DD;
    float* C = (type == 0) ? g_qp[set] : (type == 1 ? g_kp[set] : g_v[set]);
    int n0 = cb*128;

    int tid = threadIdx.x;
    int tx = tid & 15, ty = tid >> 4;

    int am  = tid >> 1;
    int akq = (tid & 1) * 4;
    int arow = row0 + am;
    int asrc = gather ? g_sidx[arow] : arow;
    const float* aptr = A + (size_t)asrc*DD + akq;
    int wk = tid >> 5;
    int wn = (tid & 31) * 4;          // float index; pair index = (tid&31)*2
    const float* wptr = W + (size_t)wk*DD + n0 + wn;
    int wp = (tid & 31) * 2;

    float2 acc2[8][4];
#pragma unroll
    for (int i = 0; i < 8; i++)
#pragma unroll
        for (int j = 0; j < 4; j++) acc2[i][j] = make_float2(0.f, 0.f);

    for (int k0 = 0; k0 < DD; k0 += 8) {
        float4 av = *(const float4*)(aptr + k0);
        float4 wv = *(const float4*)(wptr + (size_t)k0*DD);
        As2[akq+0][am] = make_float2(av.x, av.x);
        As2[akq+1][am] = make_float2(av.y, av.y);
        As2[akq+2][am] = make_float2(av.z, av.z);
        As2[akq+3][am] = make_float2(av.w, av.w);
        Ws2[wk][wp]   = make_float2(wv.x, wv.y);
        Ws2[wk][wp+1] = make_float2(wv.z, wv.w);
        __syncthreads();
#pragma unroll
        for (int kk = 0; kk < 8; kk++) {
            float2 a[8], bfr[4];
#pragma unroll
            for (int i = 0; i < 8; i++) a[i] = As2[kk][ty*8 + i];
#pragma unroll
            for (int j = 0; j < 4; j++) bfr[j] = Ws2[kk][tx*4 + j];
#pragma unroll
            for (int i = 0; i < 8; i++)
#pragma unroll
                for (int j = 0; j < 4; j++) fma2(acc2[i][j], a[i], bfr[j]);
        }
        __syncthreads();
    }

    float bj[8];
#pragma unroll
    for (int j = 0; j < 8; j++) bj[j] = bi[n0 + tx*8 + j];
#pragma unroll
    for (int i = 0; i < 8; i++) {
        int row = row0 + ty*8 + i;
        float* crow = C + (size_t)row*DD + n0 + tx*8;
        float4 o0, o1;
        o0.x = acc2[i][0].x+bj[0]; o0.y = acc2[i][0].y+bj[1];
        o0.z = acc2[i][1].x+bj[2]; o0.w = acc2[i][1].y+bj[3];
        o1.x = acc2[i][2].x+bj[4]; o1.y = acc2[i][2].y+bj[5];
        o1.z = acc2[i][3].x+bj[6]; o1.w = acc2[i][3].y+bj[7];
        *(float4*)crow       = o0;
        *(float4*)(crow + 4) = o1;
    }
}

// ---------------- voh: batched GEMM voh[r,h,:] = v[r, h*32:+32] @ Wout[h*32:+32, :] ----------------
// grid: x = 24 row-tiles(128), y = 2 col-tiles(128), z = set*8+h ; K=32 single pass
__global__ __launch_bounds__(256) void k_voh(const float* __restrict__ W1, const float* __restrict__ W2) {
    int set = blockIdx.z >> 3, h = blockIdx.z & 7;
    const float* Wout = (set ? W2 : W1) + 3*DD*DD + h*DPH*DD;
    const float* V = g_v[set];
    int r0 = blockIdx.x * 128, n0 = blockIdx.y * 128;

    __shared__ float2 As2[32][128];  // 32 KB, duplicated
    __shared__ float2 Ws2[32][64];   // 16 KB

    int tid = threadIdx.x;
    int tx = tid & 15, ty = tid >> 4;

    // load A: 128 rows x 32 k
    {
        int rr = tid >> 1, kq = (tid & 1) * 16;
        const float* ap = V + (size_t)(r0 + rr)*DD + h*DPH + kq;
#pragma unroll
        for (int c = 0; c < 4; c++) {
            float4 av = *(const float4*)(ap + c*4);
            As2[kq + c*4 + 0][rr] = make_float2(av.x, av.x);
            As2[kq + c*4 + 1][rr] = make_float2(av.y, av.y);
            As2[kq + c*4 + 2][rr] = make_float2(av.z, av.z);
            As2[kq + c*4 + 3][rr] = make_float2(av.w, av.w);
        }
    }
    // load W: 32 k x 128 n
    {
        int wk = tid >> 5, wp = (tid & 31) * 2, wn = (tid & 31) * 4;
#pragma unroll
        for (int s = 0; s < 4; s++) {
            float4 wv = *(const float4*)(Wout + (size_t)(wk + 8*s)*DD + n0 + wn);
            Ws2[wk + 8*s][wp]   = make_float2(wv.x, wv.y);
            Ws2[wk + 8*s][wp+1] = make_float2(wv.z, wv.w);
        }
    }
    __syncthreads();

    float2 acc2[8][4];
#pragma unroll
    for (int i = 0; i < 8; i++)
#pragma unroll
        for (int j = 0; j < 4; j++) acc2[i][j] = make_float2(0.f, 0.f);

#pragma unroll
    for (int kk = 0; kk < 32; kk++) {
        float2 a[8], bfr[4];
#pragma unroll
        for (int i = 0; i < 8; i++) a[i] = As2[kk][ty*8 + i];
#pragma unroll
        for (int j = 0; j < 4; j++) bfr[j] = Ws2[kk][tx*4 + j];
#pragma unroll
        for (int i = 0; i < 8; i++)
#pragma unroll
            for (int j = 0; j < 4; j++) fma2(acc2[i][j], a[i], bfr[j]);
    }

#pragma unroll
    for (int i = 0; i < 8; i++) {
        int row = r0 + ty*8 + i;
        float* op = g_voh[set] + ((size_t)row*HH + h)*DD + n0 + tx*8;
        float4 o0, o1;
        o0.x = acc2[i][0].x; o0.y = acc2[i][0].y; o0.z = acc2[i][1].x; o0.w = acc2[i][1].y;
        o1.x = acc2[i][2].x; o1.y = acc2[i][2].y; o1.z = acc2[i][3].x; o1.w = acc2[i][3].y;
        *(float4*)op       = o0;
        *(float4*)(op + 4) = o1;
    }
}

// ---------------- scores ----------------
__global__ void k_scores() {
    int h = blockIdx.x, b = blockIdx.y, set = blockIdx.z;
    __shared__ float qh[EE][DPH + 1];
    __shared__ float kh[MM][DPH + 1];
    int tid = threadIdx.x;

    for (int i = tid; i < EE*DPH; i += 256) {
        int j = i >> 5, d = i & 31;
        qh[j][d] = g_qp[set][(b*EE + j)*DD + h*DPH + d];
    }
    for (int i = tid; i < MM*DPH; i += 256) {
        int m = i >> 5, d = i & 31;
        kh[m][d] = g_kp[set][(b*MM + m)*DD + h*DPH + d];
    }
    __syncthreads();

    const float scale = 0.17677669529663687f;
    for (int idx = tid; idx < EE*MM; idx += 256) {
        int j = idx / MM, m = idx % MM;
        float acc = 0.f;
#pragma unroll
        for (int d = 0; d < DPH; d++) acc += qh[j][d] * kh[m][d];
        g_sc[set][((b*EE + j)*HH + h)*MM + m] = acc * scale;
    }
}

// ---------------- combine: V row cached in regs, alpha broadcast, shuffle LN ----------------
__global__ __launch_bounds__(256) void k_combine(
    const float* __restrict__ ent,
    const float* __restrict__ b1, const float* __restrict__ ln1,
    const float* __restrict__ b2, const float* __restrict__ ln2,
    float* __restrict__ out)
{
    int e = blockIdx.x, b = blockIdx.y, set = blockIdx.z;
    int tid = threadIdx.x, lane = tid & 31, wid = tid >> 5;

    __shared__ int   ml[MAXML];
    __shared__ float mxs[EE*HH];
    __shared__ float ise[EE*HH];
    __shared__ float alpha_s[EE*HH*IC];
    __shared__ float Vs[IC*HH][DD];

    int cnt = g_mcnt[b*EE + e];
    if (tid < MAXML) ml[tid] = (tid < cnt) ? g_mlist[(b*EE + e)*MAXML + tid] : 0;
    __syncthreads();

    const float* scb = g_sc[set] + (size_t)b*EE*HH*MM;

    // per (q,h) softmax max + inverse sum
    for (int t = tid; t < EE*HH; t += 256) {
        const float* sp = scb + t*MM;
        float mx = -1e30f;
        for (int i = 0; i < cnt; i++) mx = fmaxf(mx, sp[ml[i]]);
        float s = 0.f;
        for (int i = 0; i < cnt; i++) s += __expf(sp[ml[i]] - mx);
        mxs[t] = mx; ise[t] = 1.f / s;
    }

    // thread owns d = lane*4+j (j<4) and d = 128+lane*4+(j-4)
    const float* bb = (set ? b2 : b1) + 3*DD;
    const float* ln = (set ? ln2 : ln1);
    int d0 = lane*4, d1 = 128 + lane*4;
    float4 bo0 = *(const float4*)(bb + d0),       bo1 = *(const float4*)(bb + d1);
    float4 gm0 = *(const float4*)(ln + d0),       gm1 = *(const float4*)(ln + d1);
    float4 bt0 = *(const float4*)(ln + DD + d0),  bt1 = *(const float4*)(ln + DD + d1);

    float acc[6][8];
#pragma unroll
    for (int t = 0; t < 6; t++)
#pragma unroll
        for (int j = 0; j < 8; j++) acc[t][j] = 0.f;

    __syncthreads();

    for (int ic0 = 0; ic0 < cnt; ic0 += IC) {
        int icn = min(IC, cnt - ic0);
        int rows = icn * HH;
        // stage V rows into shared (float4)
        for (int idx = tid; idx < rows*64; idx += 256) {
            int rr = idx >> 6, dq = (idx & 63) * 4;
            int ii = rr >> 3, h = rr & 7;
            int m = ml[ic0 + ii];
            *(float4*)&Vs[rr][dq] =
                *(const float4*)(g_voh[set] + (((size_t)(b*MM + m))*HH + h)*DD + dq);
        }
        // normalized alphas
        for (int t = tid; t < EE*HH*icn; t += 256) {
            int qh = t / icn, ii = t - qh*icn;
            float sv = scb[qh*MM + ml[ic0 + ii]];
            alpha_s[qh*IC + ii] = __expf(sv - mxs[qh]) * ise[qh];
        }
        __syncthreads();

        for (int p = 0; p < rows; p++) {
            int ii = p >> 3, h = p & 7;
            float4 v0 = *(float4*)&Vs[p][d0];
            float4 v1 = *(float4*)&Vs[p][d1];
#pragma unroll
            for (int t = 0; t < 6; t++) {
                int q = wid + 8*t;
                float a = alpha_s[(q*HH + h)*IC + ii];   // broadcast within warp
                acc[t][0] += a*v0.x; acc[t][1] += a*v0.y;
                acc[t][2] += a*v0.z; acc[t][3] += a*v0.w;
                acc[t][4] += a*v1.x; acc[t][5] += a*v1.y;
                acc[t][6] += a*v1.z; acc[t][7] += a*v1.w;
            }
        }
        __syncthreads();
    }

    // epilogue: bias + residual + LayerNorm + write
#pragma unroll
    for (int t = 0; t < 6; t++) {
        int q = wid + 8*t;
        const float* er = ent + (size_t)(b*EE + q)*DD;
        float4 e0 = *(const float4*)(er + d0);
        float4 e1 = *(const float4*)(er + d1);
        float x[8];
        x[0] = acc[t][0] + bo0.x + e0.x; x[1] = acc[t][1] + bo0.y + e0.y;
        x[2] = acc[t][2] + bo0.z + e0.z; x[3] = acc[t][3] + bo0.w + e0.w;
        x[4] = acc[t][4] + bo1.x + e1.x; x[5] = acc[t][5] + bo1.y + e1.y;
        x[6] = acc[t][6] + bo1.z + e1.z; x[7] = acc[t][7] + bo1.w + e1.w;
        float sm = 0.f;
#pragma unroll
        for (int j = 0; j < 8; j++) sm += x[j];
#pragma unroll
        for (int o = 16; o > 0; o >>= 1) sm += __shfl_xor_sync(0xffffffffu, sm, o);
        float mu = sm * (1.f/DD);
        float vv = 0.f;
#pragma unroll
        for (int j = 0; j < 8; j++) { x[j] -= mu; vv += x[j]*x[j]; }
#pragma unroll
        for (int o = 16; o > 0; o >>= 1) vv += __shfl_xor_sync(0xffffffffu, vv, o);
        float rs = rsqrtf(vv*(1.f/DD) + 1e-5f);

        int orow = set ? (q*EE + e) : (e*EE + q);
        float* op = out + ((size_t)set*BB*PAIRS + (size_t)b*PAIRS + orow)*DD;
        float4 o0, o1;
        o0.x = x[0]*rs*gm0.x + bt0.x; o0.y = x[1]*rs*gm0.y + bt0.y;
        o0.z = x[2]*rs*gm0.z + bt0.z; o0.w = x[3]*rs*gm0.w + bt0.w;
        o1.x = x[4]*rs*gm1.x + bt1.x; o1.y = x[5]*rs*gm1.y + bt1.y;
        o1.z = x[6]*rs*gm1.z + bt1.z; o1.w = x[7]*rs*gm1.w + bt1.w;
        *(float4*)(op + d0) = o0;
        *(float4*)(op + d1) = o1;
    }
}

// ---------------- launch ----------------
extern "C" void kernel_launch(void* const* d_in, const int* in_sizes, int n_in,
                              void* d_out, int out_size) {
    const void*  info = d_in[0];
    const float* ent  = (const float*)d_in[2];
    const float* men  = (const float*)d_in[3];
    const float* sen  = (const float*)d_in[4];
    const float* W1   = (const float*)d_in[5];
    const float* b1   = (const float*)d_in[6];
    const float* ln1  = (const float*)d_in[7];
    const float* W2   = (const float*)d_in[8];
    const float* b2   = (const float*)d_in[9];
    const float* ln2  = (const float*)d_in[10];
    float* out = (float*)d_out;

    k_prep<<<1, 256>>>(info);
    k_proj_all<<<240, 256>>>(ent, men, sen, W1, b1, W2, b2);
    k_voh   <<<dim3(24, 2, 16), 256>>>(W1, W2);
    k_scores<<<dim3(HH, BB, 2), 256>>>();
    k_combine<<<dim3(EE, BB, 2), 256>>>(ent, b1, ln1, b2, ln2, out);
}

// round 5
// speedup vs baseline: 2.6351x; 1.0914x over previous
#include <cuda_runtime.h>

#define BB   32
#define EE   48
#define MM   96
#define DD   256
#define HH   8
#define DPH  32
#define PAIRS (EE*EE)
#define MAXML 64
#define IC   4
#define SCAP 8

// ---------------- scratch ----------------
__device__ int   g_sidx[BB*MM];
__device__ int   g_mid [BB*MM];
__device__ int   g_mlist[BB*EE*MAXML];
__device__ int   g_mcnt [BB*EE];
__device__ float g_qp [2][BB*EE*DD];
__device__ float g_kp [2][BB*MM*DD];
__device__ float g_v  [2][BB*MM*DD];
__device__ float g_voh[2][BB*MM*HH*DD];
__device__ float g_sc [2][BB*EE*HH*MM];

__device__ __forceinline__ void fma2(float2& d, float2 a, float2 b) {
    unsigned long long dd = *(unsigned long long*)&d;
    unsigned long long aa = *(unsigned long long*)&a;
    unsigned long long bb = *(unsigned long long*)&b;
    asm("fma.rn.f32x2 %0, %1, %2, %0;" : "+l"(dd) : "l"(aa), "l"(bb));
    d = *(float2*)&dd;
}

// ---------------- prep ----------------
__global__ void k_prep(const void* info) {
    int tid = threadIdx.x;
    __shared__ int s[256];
    const int* p32 = (const int*)info;
    int mx = 0;
    for (int r = tid; r < BB*MM; r += 256) mx = max(mx, p32[r*6 + 4]);
    s[tid] = mx; __syncthreads();
    for (int o = 128; o > 0; o >>= 1) { if (tid < o) s[tid] = max(s[tid], s[tid+o]); __syncthreads(); }
    int is32 = (s[0] > 0);
    for (int r = tid; r < BB*MM; r += 256) {
        int e, sidx;
        if (is32) { e = p32[r*6 + 0]; sidx = p32[r*6 + 4]; }
        else {
            const long long* p64 = (const long long*)info;
            e = (int)p64[r*6 + 0]; sidx = (int)p64[r*6 + 4];
        }
        g_mid[r] = e; g_sidx[r] = sidx;
    }
    __syncthreads();
    for (int t = tid; t < BB*EE; t += 256) {
        int b = t / EE;
        int cnt = 0;
        for (int m = 0; m < MM; m++) {
            if (g_mid[b*MM + m] == t && cnt < MAXML)
                g_mlist[t*MAXML + cnt++] = m;
        }
        g_mcnt[t] = cnt;
    }
}

// ---------------- all 6 projections: 128x128 tiles, KSTEP=16, f32x2 ----------------
__global__ __launch_bounds__(256, 2) void k_proj_all(
    const float* __restrict__ ent, const float* __restrict__ men, const float* __restrict__ sen,
    const float* __restrict__ W1, const float* __restrict__ b1,
    const float* __restrict__ W2, const float* __restrict__ b2)
{
    __shared__ float2 As2[16][128];   // 16 KB, duplicated {a,a}
    __shared__ float2 Ws2[16][64];    // 8 KB

    int blk = blockIdx.x;
    int cb = blk & 1, rb = blk >> 1;
    int set = rb / 60; int r = rb % 60;
    const float* A; int gather = 0, type, row0;
    if (r < 12)      { type = 0; row0 = r*128;      A = ent; }
    else if (r < 36) { type = 1; row0 = (r-12)*128; A = sen; gather = 1; }
    else             { type = 2; row0 = (r-36)*128; A = men; }
    const float* W  = (set ? W2 : W1) + type*DD*DD;
    const float* bi = (set ? b2 : b1) + type*DD;
    float* C = (type == 0) ? g_qp[set] : (type == 1 ? g_kp[set] : g_v[set]);
    int n0 = cb*128;

    int tid = threadIdx.x;
    int tx = tid & 15, ty = tid >> 4;

    // A loader: thread -> row (tid>>1), 8 consecutive k at (tid&1)*8
    int am  = tid >> 1;
    int akq = (tid & 1) * 8;
    int arow = row0 + am;
    int asrc = gather ? g_sidx[arow] : arow;
    const float* aptr = A + (size_t)asrc*DD + akq;
    // W loader: thread -> k row (tid>>4), 8 consecutive n at (tid&15)*8
    int wk = tid >> 4;
    int wn = (tid & 15) * 8;
    const float* wptr = W + (size_t)wk*DD + n0 + wn;
    int wp = (tid & 15) * 4;

    float2 acc2[8][4];
#pragma unroll
    for (int i = 0; i < 8; i++)
#pragma unroll
        for (int j = 0; j < 4; j++) acc2[i][j] = make_float2(0.f, 0.f);

    for (int k0 = 0; k0 < DD; k0 += 16) {
        float4 a0 = *(const float4*)(aptr + k0);
        float4 a1 = *(const float4*)(aptr + k0 + 4);
        float4 w0 = *(const float4*)(wptr + (size_t)k0*DD);
        float4 w1 = *(const float4*)(wptr + (size_t)k0*DD + 4);
        As2[akq+0][am] = make_float2(a0.x, a0.x);
        As2[akq+1][am] = make_float2(a0.y, a0.y);
        As2[akq+2][am] = make_float2(a0.z, a0.z);
        As2[akq+3][am] = make_float2(a0.w, a0.w);
        As2[akq+4][am] = make_float2(a1.x, a1.x);
        As2[akq+5][am] = make_float2(a1.y, a1.y);
        As2[akq+6][am] = make_float2(a1.z, a1.z);
        As2[akq+7][am] = make_float2(a1.w, a1.w);
        Ws2[wk][wp]   = make_float2(w0.x, w0.y);
        Ws2[wk][wp+1] = make_float2(w0.z, w0.w);
        Ws2[wk][wp+2] = make_float2(w1.x, w1.y);
        Ws2[wk][wp+3] = make_float2(w1.z, w1.w);
        __syncthreads();
#pragma unroll
        for (int kk = 0; kk < 16; kk++) {
            float2 a[8], bfr[4];
#pragma unroll
            for (int i = 0; i < 8; i++) a[i] = As2[kk][ty*8 + i];
#pragma unroll
            for (int j = 0; j < 4; j++) bfr[j] = Ws2[kk][tx*4 + j];
#pragma unroll
            for (int i = 0; i < 8; i++)
#pragma unroll
                for (int j = 0; j < 4; j++) fma2(acc2[i][j], a[i], bfr[j]);
        }
        __syncthreads();
    }

    float bj[8];
#pragma unroll
    for (int j = 0; j < 8; j++) bj[j] = bi[n0 + tx*8 + j];
#pragma unroll
    for (int i = 0; i < 8; i++) {
        int row = row0 + ty*8 + i;
        float* crow = C + (size_t)row*DD + n0 + tx*8;
        float4 o0, o1;
        o0.x = acc2[i][0].x+bj[0]; o0.y = acc2[i][0].y+bj[1];
        o0.z = acc2[i][1].x+bj[2]; o0.w = acc2[i][1].y+bj[3];
        o1.x = acc2[i][2].x+bj[4]; o1.y = acc2[i][2].y+bj[5];
        o1.z = acc2[i][3].x+bj[6]; o1.w = acc2[i][3].y+bj[7];
        *(float4*)crow       = o0;
        *(float4*)(crow + 4) = o1;
    }
}

// ---------------- fused voh (blocks 0..767) + scores (blocks 768..1279) ----------------
struct SmemVoh { float2 As2[32][128]; float2 Ws2[32][64]; };   // 48 KB
struct SmemSc  { float qh[32][48]; float kh[32][96]; };        // 18 KB

__global__ __launch_bounds__(256) void k_vs(const float* __restrict__ W1, const float* __restrict__ W2) {
    __shared__ union { SmemVoh v; SmemSc s; } sm;
    int bx = blockIdx.x;
    int tid = threadIdx.x;

    if (bx < 768) {
        // ---- voh: voh[r,h,:] = v[r, h*32:+32] @ Wout_h ----
        int x = bx % 24, rest = bx / 24;
        int y = rest & 1, z = rest >> 1;
        int set = z >> 3, h = z & 7;
        const float* Wout = (set ? W2 : W1) + 3*DD*DD + h*DPH*DD;
        const float* V = g_v[set];
        int r0 = x * 128, n0 = y * 128;
        int tx = tid & 15, ty = tid >> 4;

        {
            int rr = tid >> 1, kq = (tid & 1) * 16;
            const float* ap = V + (size_t)(r0 + rr)*DD + h*DPH + kq;
#pragma unroll
            for (int c = 0; c < 4; c++) {
                float4 av = *(const float4*)(ap + c*4);
                sm.v.As2[kq + c*4 + 0][rr] = make_float2(av.x, av.x);
                sm.v.As2[kq + c*4 + 1][rr] = make_float2(av.y, av.y);
                sm.v.As2[kq + c*4 + 2][rr] = make_float2(av.z, av.z);
                sm.v.As2[kq + c*4 + 3][rr] = make_float2(av.w, av.w);
            }
        }
        {
            int wk = tid >> 5, wp = (tid & 31) * 2, wn = (tid & 31) * 4;
#pragma unroll
            for (int s = 0; s < 4; s++) {
                float4 wv = *(const float4*)(Wout + (size_t)(wk + 8*s)*DD + n0 + wn);
                sm.v.Ws2[wk + 8*s][wp]   = make_float2(wv.x, wv.y);
                sm.v.Ws2[wk + 8*s][wp+1] = make_float2(wv.z, wv.w);
            }
        }
        __syncthreads();

        float2 acc2[8][4];
#pragma unroll
        for (int i = 0; i < 8; i++)
#pragma unroll
            for (int j = 0; j < 4; j++) acc2[i][j] = make_float2(0.f, 0.f);

#pragma unroll
        for (int kk = 0; kk < 32; kk++) {
            float2 a[8], bfr[4];
#pragma unroll
            for (int i = 0; i < 8; i++) a[i] = sm.v.As2[kk][ty*8 + i];
#pragma unroll
            for (int j = 0; j < 4; j++) bfr[j] = sm.v.Ws2[kk][tx*4 + j];
#pragma unroll
            for (int i = 0; i < 8; i++)
#pragma unroll
                for (int j = 0; j < 4; j++) fma2(acc2[i][j], a[i], bfr[j]);
        }

#pragma unroll
        for (int i = 0; i < 8; i++) {
            int row = r0 + ty*8 + i;
            float* op = g_voh[set] + ((size_t)row*HH + h)*DD + n0 + tx*8;
            float4 o0, o1;
            o0.x = acc2[i][0].x; o0.y = acc2[i][0].y; o0.z = acc2[i][1].x; o0.w = acc2[i][1].y;
            o1.x = acc2[i][2].x; o1.y = acc2[i][2].y; o1.z = acc2[i][3].x; o1.w = acc2[i][3].y;
            *(float4*)op       = o0;
            *(float4*)(op + 4) = o1;
        }
    } else {
        // ---- scores: register-tiled 3q x 6m per thread ----
        int id = bx - 768;
        int h = id & 7, b = (id >> 3) & 31, set = id >> 8;

        for (int i = tid; i < EE*DPH; i += 256) {
            int q = i >> 5, d = i & 31;
            sm.s.qh[d][q] = g_qp[set][(b*EE + q)*DD + h*DPH + d];
        }
        for (int i = tid; i < MM*DPH; i += 256) {
            int m = i >> 5, d = i & 31;
            sm.s.kh[d][m] = g_kp[set][(b*MM + m)*DD + h*DPH + d];
        }
        __syncthreads();

        int q0 = (tid >> 4) * 3;
        int m0 = (tid & 15) * 6;
        float acc[3][6];
#pragma unroll
        for (int i = 0; i < 3; i++)
#pragma unroll
            for (int j = 0; j < 6; j++) acc[i][j] = 0.f;

#pragma unroll 8
        for (int kk = 0; kk < DPH; kk++) {
            float qv[3], kv[6];
#pragma unroll
            for (int i = 0; i < 3; i++) qv[i] = sm.s.qh[kk][q0 + i];
#pragma unroll
            for (int j = 0; j < 6; j++) kv[j] = sm.s.kh[kk][m0 + j];
#pragma unroll
            for (int i = 0; i < 3; i++)
#pragma unroll
                for (int j = 0; j < 6; j++) acc[i][j] += qv[i] * kv[j];
        }

        const float scale = 0.17677669529663687f;
#pragma unroll
        for (int i = 0; i < 3; i++) {
            float* sp = &g_sc[set][((size_t)(b*EE + q0 + i)*HH + h)*MM + m0];
#pragma unroll
            for (int j = 0; j < 6; j++) sp[j] = acc[i][j] * scale;
        }
    }
}

// ---------------- combine: staged-score softmax + V reg cache + shuffle LN ----------------
__global__ __launch_bounds__(256) void k_combine(
    const float* __restrict__ ent,
    const float* __restrict__ b1, const float* __restrict__ ln1,
    const float* __restrict__ b2, const float* __restrict__ ln2,
    float* __restrict__ out)
{
    int e = blockIdx.x, b = blockIdx.y, set = blockIdx.z;
    int tid = threadIdx.x, lane = tid & 31, wid = tid >> 5;

    __shared__ int   ml[MAXML];
    __shared__ union {
        float scs[EE*HH][SCAP];                         // fast path: staged scores -> alphas
        struct { float mxs[EE*HH]; float ise[EE*HH]; float alpha[EE*HH*IC]; } sl;  // slow path
    } u;
    __shared__ float Vs[IC*HH][DD];

    int cnt = g_mcnt[b*EE + e];
    if (tid < MAXML) ml[tid] = (tid < cnt) ? g_mlist[(b*EE + e)*MAXML + tid] : 0;
    __syncthreads();

    const float* scb = g_sc[set] + (size_t)b*EE*HH*MM;
    bool fast = (cnt <= SCAP);

    if (fast) {
        // cooperative stage of all needed scores (one global pass), then in-place alphas
        for (int idx = tid; idx < EE*HH*cnt; idx += 256) {
            int qh = idx / cnt, i = idx - qh*cnt;
            u.scs[qh][i] = scb[qh*MM + ml[i]];
        }
        __syncthreads();
        for (int t = tid; t < EE*HH; t += 256) {
            float mx = -1e30f;
#pragma unroll
            for (int i = 0; i < SCAP; i++) if (i < cnt) mx = fmaxf(mx, u.scs[t][i]);
            float s = 0.f;
#pragma unroll
            for (int i = 0; i < SCAP; i++) if (i < cnt) s += __expf(u.scs[t][i] - mx);
            float inv = 1.f / s;
#pragma unroll
            for (int i = 0; i < SCAP; i++) if (i < cnt) u.scs[t][i] = __expf(u.scs[t][i] - mx) * inv;
        }
    } else {
        for (int t = tid; t < EE*HH; t += 256) {
            const float* sp = scb + t*MM;
            float mx = -1e30f;
            for (int i = 0; i < cnt; i++) mx = fmaxf(mx, sp[ml[i]]);
            float s = 0.f;
            for (int i = 0; i < cnt; i++) s += __expf(sp[ml[i]] - mx);
            u.sl.mxs[t] = mx; u.sl.ise[t] = 1.f / s;
        }
    }

    const float* bb = (set ? b2 : b1) + 3*DD;
    const float* ln = (set ? ln2 : ln1);
    int d0 = lane*4, d1 = 128 + lane*4;
    float4 bo0 = *(const float4*)(bb + d0),       bo1 = *(const float4*)(bb + d1);
    float4 gm0 = *(const float4*)(ln + d0),       gm1 = *(const float4*)(ln + d1);
    float4 bt0 = *(const float4*)(ln + DD + d0),  bt1 = *(const float4*)(ln + DD + d1);

    float acc[6][8];
#pragma unroll
    for (int t = 0; t < 6; t++)
#pragma unroll
        for (int j = 0; j < 8; j++) acc[t][j] = 0.f;

    __syncthreads();

    for (int ic0 = 0; ic0 < cnt; ic0 += IC) {
        int icn = min(IC, cnt - ic0);
        int rows = icn * HH;
        for (int idx = tid; idx < rows*64; idx += 256) {
            int rr = idx >> 6, dq = (idx & 63) * 4;
            int ii = rr >> 3, h = rr & 7;
            int m = ml[ic0 + ii];
            *(float4*)&Vs[rr][dq] =
                *(const float4*)(g_voh[set] + (((size_t)(b*MM + m))*HH + h)*DD + dq);
        }
        if (!fast) {
            for (int t = tid; t < EE*HH*icn; t += 256) {
                int qh = t / icn, ii = t - qh*icn;
                float sv = scb[qh*MM + ml[ic0 + ii]];
                u.sl.alpha[qh*IC + ii] = __expf(sv - u.sl.mxs[qh]) * u.sl.ise[qh];
            }
        }
        __syncthreads();

        for (int p = 0; p < rows; p++) {
            int ii = p >> 3, h = p & 7;
            float4 v0 = *(float4*)&Vs[p][d0];
            float4 v1 = *(float4*)&Vs[p][d1];
#pragma unroll
            for (int t = 0; t < 6; t++) {
                int q = wid + 8*t;
                float a = fast ? u.scs[q*HH + h][ic0 + ii]
                               : u.sl.alpha[(q*HH + h)*IC + ii];
                acc[t][0] += a*v0.x; acc[t][1] += a*v0.y;
                acc[t][2] += a*v0.z; acc[t][3] += a*v0.w;
                acc[t][4] += a*v1.x; acc[t][5] += a*v1.y;
                acc[t][6] += a*v1.z; acc[t][7] += a*v1.w;
            }
        }
        __syncthreads();
    }

#pragma unroll
    for (int t = 0; t < 6; t++) {
        int q = wid + 8*t;
        const float* er = ent + (size_t)(b*EE + q)*DD;
        float4 e0 = *(const float4*)(er + d0);
        float4 e1 = *(const float4*)(er + d1);
        float x[8];
        x[0] = acc[t][0] + bo0.x + e0.x; x[1] = acc[t][1] + bo0.y + e0.y;
        x[2] = acc[t][2] + bo0.z + e0.z; x[3] = acc[t][3] + bo0.w + e0.w;
        x[4] = acc[t][4] + bo1.x + e1.x; x[5] = acc[t][5] + bo1.y + e1.y;
        x[6] = acc[t][6] + bo1.z + e1.z; x[7] = acc[t][7] + bo1.w + e1.w;
        float sm = 0.f;
#pragma unroll
        for (int j = 0; j < 8; j++) sm += x[j];
#pragma unroll
        for (int o = 16; o > 0; o >>= 1) sm += __shfl_xor_sync(0xffffffffu, sm, o);
        float mu = sm * (1.f/DD);
        float vv = 0.f;
#pragma unroll
        for (int j = 0; j < 8; j++) { x[j] -= mu; vv += x[j]*x[j]; }
#pragma unroll
        for (int o = 16; o > 0; o >>= 1) vv += __shfl_xor_sync(0xffffffffu, vv, o);
        float rs = rsqrtf(vv*(1.f/DD) + 1e-5f);

        int orow = set ? (q*EE + e) : (e*EE + q);
        float* op = out + ((size_t)set*BB*PAIRS + (size_t)b*PAIRS + orow)*DD;
        float4 o0, o1;
        o0.x = x[0]*rs*gm0.x + bt0.x; o0.y = x[1]*rs*gm0.y + bt0.y;
        o0.z = x[2]*rs*gm0.z + bt0.z; o0.w = x[3]*rs*gm0.w + bt0.w;
        o1.x = x[4]*rs*gm1.x + bt1.x; o1.y = x[5]*rs*gm1.y + bt1.y;
        o1.z = x[6]*rs*gm1.z + bt1.z; o1.w = x[7]*rs*gm1.w + bt1.w;
        *(float4*)(op + d0) = o0;
        *(float4*)(op + d1) = o1;
    }
}

// ---------------- launch ----------------
extern "C" void kernel_launch(void* const* d_in, const int* in_sizes, int n_in,
                              void* d_out, int out_size) {
    const void*  info = d_in[0];
    const float* ent  = (const float*)d_in[2];
    const float* men  = (const float*)d_in[3];
    const float* sen  = (const float*)d_in[4];
    const float* W1   = (const float*)d_in[5];
    const float* b1   = (const float*)d_in[6];
    const float* ln1  = (const float*)d_in[7];
    const float* W2   = (const float*)d_in[8];
    const float* b2   = (const float*)d_in[9];
    const float* ln2  = (const float*)d_in[10];
    float* out = (float*)d_out;

    k_prep<<<1, 256>>>(info);
    k_proj_all<<<240, 256>>>(ent, men, sen, W1, b1, W2, b2);
    k_vs<<<1280, 256>>>(W1, W2);
    k_combine<<<dim3(EE, BB, 2), 256>>>(ent, b1, ln1, b2, ln2, out);
}

// round 6
// speedup vs baseline: 3.2024x; 1.2153x over previous
#include <cuda_runtime.h>

#define BB   32
#define EE   48
#define MM   96
#define DD   256
#define HH   8
#define DPH  32
#define PAIRS (EE*EE)
#define MAXML 64
#define IC   4
#define SCAP 8

// ---------------- scratch ----------------
__device__ int   g_sidx[BB*MM];
__device__ int   g_mlist[BB*EE*MAXML];
__device__ int   g_mcnt [BB*EE];
__device__ float g_qp [2][BB*EE*DD];
__device__ float g_kp [2][BB*MM*DD];
__device__ float g_v  [2][BB*MM*DD];
__device__ float g_voh[2][BB*MM*HH*DD];
__device__ float g_sc [2][BB*EE*HH*MM];

__device__ __forceinline__ void fma2(float2& d, float2 a, float2 b) {
    unsigned long long dd = *(unsigned long long*)&d;
    unsigned long long aa = *(unsigned long long*)&a;
    unsigned long long bb = *(unsigned long long*)&b;
    asm("fma.rn.f32x2 %0, %1, %2, %0;" : "+l"(dd) : "l"(aa), "l"(bb));
    d = *(float2*)&dd;
}

// ---------------- prep: one block per doc ----------------
__global__ void k_prep(const void* info) {
    int b = blockIdx.x, tid = threadIdx.x;
    __shared__ int smid[MM];
    __shared__ int s[128];
    const int* p32 = (const int*)info;
    // dtype detect (scan whole info; int64-LE read as int32 puts zeros at r*6+4)
    int mx = 0;
    for (int r = tid; r < BB*MM; r += 128) mx = max(mx, p32[r*6 + 4]);
    s[tid] = mx; __syncthreads();
    for (int o = 64; o > 0; o >>= 1) { if (tid < o) s[tid] = max(s[tid], s[tid+o]); __syncthreads(); }
    int is32 = (s[0] > 0);
    // extract this doc's rows
    for (int m = tid; m < MM; m += 128) {
        int r = b*MM + m;
        int e, sidx;
        if (is32) { e = p32[r*6 + 0]; sidx = p32[r*6 + 4]; }
        else {
            const long long* p64 = (const long long*)info;
            e = (int)p64[r*6 + 0]; sidx = (int)p64[r*6 + 4];
        }
        smid[m] = e; g_sidx[r] = sidx;
    }
    __syncthreads();
    // mention lists for this doc's 48 entities (scan shared)
    for (int e = tid; e < EE; e += 128) {
        int target = b*EE + e;
        int cnt = 0;
        for (int m = 0; m < MM; m++) {
            if (smid[m] == target && cnt < MAXML)
                g_mlist[target*MAXML + cnt++] = m;
        }
        g_mcnt[target] = cnt;
    }
}

// ---------------- all 6 projections: 128x128 tiles, KSTEP=16, f32x2 ----------------
__global__ __launch_bounds__(256, 2) void k_proj_all(
    const float* __restrict__ ent, const float* __restrict__ men, const float* __restrict__ sen,
    const float* __restrict__ W1, const float* __restrict__ b1,
    const float* __restrict__ W2, const float* __restrict__ b2)
{
    __shared__ float2 As2[16][128];
    __shared__ float2 Ws2[16][64];

    int blk = blockIdx.x;
    int cb = blk & 1, rb = blk >> 1;
    int set = rb / 60; int r = rb % 60;
    const float* A; int gather = 0, type, row0;
    if (r < 12)      { type = 0; row0 = r*128;      A = ent; }
    else if (r < 36) { type = 1; row0 = (r-12)*128; A = sen; gather = 1; }
    else             { type = 2; row0 = (r-36)*128; A = men; }
    const float* W  = (set ? W2 : W1) + type*DD*DD;
    const float* bi = (set ? b2 : b1) + type*DD;
    float* C = (type == 0) ? g_qp[set] : (type == 1 ? g_kp[set] : g_v[set]);
    int n0 = cb*128;

    int tid = threadIdx.x;
    int tx = tid & 15, ty = tid >> 4;

    int am  = tid >> 1;
    int akq = (tid & 1) * 8;
    int arow = row0 + am;
    int asrc = gather ? g_sidx[arow] : arow;
    const float* aptr = A + (size_t)asrc*DD + akq;
    int wk = tid >> 4;
    int wn = (tid & 15) * 8;
    const float* wptr = W + (size_t)wk*DD + n0 + wn;
    int wp = (tid & 15) * 4;

    float2 acc2[8][4];
#pragma unroll
    for (int i = 0; i < 8; i++)
#pragma unroll
        for (int j = 0; j < 4; j++) acc2[i][j] = make_float2(0.f, 0.f);

    for (int k0 = 0; k0 < DD; k0 += 16) {
        float4 a0 = *(const float4*)(aptr + k0);
        float4 a1 = *(const float4*)(aptr + k0 + 4);
        float4 w0 = *(const float4*)(wptr + (size_t)k0*DD);
        float4 w1 = *(const float4*)(wptr + (size_t)k0*DD + 4);
        As2[akq+0][am] = make_float2(a0.x, a0.x);
        As2[akq+1][am] = make_float2(a0.y, a0.y);
        As2[akq+2][am] = make_float2(a0.z, a0.z);
        As2[akq+3][am] = make_float2(a0.w, a0.w);
        As2[akq+4][am] = make_float2(a1.x, a1.x);
        As2[akq+5][am] = make_float2(a1.y, a1.y);
        As2[akq+6][am] = make_float2(a1.z, a1.z);
        As2[akq+7][am] = make_float2(a1.w, a1.w);
        Ws2[wk][wp]   = make_float2(w0.x, w0.y);
        Ws2[wk][wp+1] = make_float2(w0.z, w0.w);
        Ws2[wk][wp+2] = make_float2(w1.x, w1.y);
        Ws2[wk][wp+3] = make_float2(w1.z, w1.w);
        __syncthreads();
#pragma unroll
        for (int kk = 0; kk < 16; kk++) {
            float2 a[8], bfr[4];
#pragma unroll
            for (int i = 0; i < 8; i++) a[i] = As2[kk][ty*8 + i];
#pragma unroll
            for (int j = 0; j < 4; j++) bfr[j] = Ws2[kk][tx*4 + j];
#pragma unroll
            for (int i = 0; i < 8; i++)
#pragma unroll
                for (int j = 0; j < 4; j++) fma2(acc2[i][j], a[i], bfr[j]);
        }
        __syncthreads();
    }

    float bj[8];
#pragma unroll
    for (int j = 0; j < 8; j++) bj[j] = bi[n0 + tx*8 + j];
#pragma unroll
    for (int i = 0; i < 8; i++) {
        int row = row0 + ty*8 + i;
        float* crow = C + (size_t)row*DD + n0 + tx*8;
        float4 o0, o1;
        o0.x = acc2[i][0].x+bj[0]; o0.y = acc2[i][0].y+bj[1];
        o0.z = acc2[i][1].x+bj[2]; o0.w = acc2[i][1].y+bj[3];
        o1.x = acc2[i][2].x+bj[4]; o1.y = acc2[i][2].y+bj[5];
        o1.z = acc2[i][3].x+bj[6]; o1.w = acc2[i][3].y+bj[7];
        *(float4*)crow       = o0;
        *(float4*)(crow + 4) = o1;
    }
}

// ---------------- fused voh (blocks 0..767) + scores (blocks 768..1279) ----------------
struct SmemVoh { float2 As2[32][128]; float2 Ws2[32][64]; };
struct SmemSc  { float qh[32][48]; float kh[32][96]; };

__global__ __launch_bounds__(256) void k_vs(const float* __restrict__ W1, const float* __restrict__ W2) {
    __shared__ union { SmemVoh v; SmemSc s; } sm;
    int bx = blockIdx.x;
    int tid = threadIdx.x;

    if (bx < 768) {
        int x = bx % 24, rest = bx / 24;
        int y = rest & 1, z = rest >> 1;
        int set = z >> 3, h = z & 7;
        const float* Wout = (set ? W2 : W1) + 3*DD*DD + h*DPH*DD;
        const float* V = g_v[set];
        int r0 = x * 128, n0 = y * 128;
        int tx = tid & 15, ty = tid >> 4;

        {
            int rr = tid >> 1, kq = (tid & 1) * 16;
            const float* ap = V + (size_t)(r0 + rr)*DD + h*DPH + kq;
#pragma unroll
            for (int c = 0; c < 4; c++) {
                float4 av = *(const float4*)(ap + c*4);
                sm.v.As2[kq + c*4 + 0][rr] = make_float2(av.x, av.x);
                sm.v.As2[kq + c*4 + 1][rr] = make_float2(av.y, av.y);
                sm.v.As2[kq + c*4 + 2][rr] = make_float2(av.z, av.z);
                sm.v.As2[kq + c*4 + 3][rr] = make_float2(av.w, av.w);
            }
        }
        {
            int wk = tid >> 5, wp = (tid & 31) * 2, wn = (tid & 31) * 4;
#pragma unroll
            for (int s = 0; s < 4; s++) {
                float4 wv = *(const float4*)(Wout + (size_t)(wk + 8*s)*DD + n0 + wn);
                sm.v.Ws2[wk + 8*s][wp]   = make_float2(wv.x, wv.y);
                sm.v.Ws2[wk + 8*s][wp+1] = make_float2(wv.z, wv.w);
            }
        }
        __syncthreads();

        float2 acc2[8][4];
#pragma unroll
        for (int i = 0; i < 8; i++)
#pragma unroll
            for (int j = 0; j < 4; j++) acc2[i][j] = make_float2(0.f, 0.f);

#pragma unroll
        for (int kk = 0; kk < 32; kk++) {
            float2 a[8], bfr[4];
#pragma unroll
            for (int i = 0; i < 8; i++) a[i] = sm.v.As2[kk][ty*8 + i];
#pragma unroll
            for (int j = 0; j < 4; j++) bfr[j] = sm.v.Ws2[kk][tx*4 + j];
#pragma unroll
            for (int i = 0; i < 8; i++)
#pragma unroll
                for (int j = 0; j < 4; j++) fma2(acc2[i][j], a[i], bfr[j]);
        }

#pragma unroll
        for (int i = 0; i < 8; i++) {
            int row = r0 + ty*8 + i;
            float* op = g_voh[set] + ((size_t)row*HH + h)*DD + n0 + tx*8;
            float4 o0, o1;
            o0.x = acc2[i][0].x; o0.y = acc2[i][0].y; o0.z = acc2[i][1].x; o0.w = acc2[i][1].y;
            o1.x = acc2[i][2].x; o1.y = acc2[i][2].y; o1.z = acc2[i][3].x; o1.w = acc2[i][3].y;
            *(float4*)op       = o0;
            *(float4*)(op + 4) = o1;
        }
    } else {
        int id = bx - 768;
        int h = id & 7, b = (id >> 3) & 31, set = id >> 8;

        for (int i = tid; i < EE*DPH; i += 256) {
            int q = i >> 5, d = i & 31;
            sm.s.qh[d][q] = g_qp[set][(b*EE + q)*DD + h*DPH + d];
        }
        for (int i = tid; i < MM*DPH; i += 256) {
            int m = i >> 5, d = i & 31;
            sm.s.kh[d][m] = g_kp[set][(b*MM + m)*DD + h*DPH + d];
        }
        __syncthreads();

        int q0 = (tid >> 4) * 3;
        int m0 = (tid & 15) * 6;
        float acc[3][6];
#pragma unroll
        for (int i = 0; i < 3; i++)
#pragma unroll
            for (int j = 0; j < 6; j++) acc[i][j] = 0.f;

#pragma unroll 8
        for (int kk = 0; kk < DPH; kk++) {
            float qv[3], kv[6];
#pragma unroll
            for (int i = 0; i < 3; i++) qv[i] = sm.s.qh[kk][q0 + i];
#pragma unroll
            for (int j = 0; j < 6; j++) kv[j] = sm.s.kh[kk][m0 + j];
#pragma unroll
            for (int i = 0; i < 3; i++)
#pragma unroll
                for (int j = 0; j < 6; j++) acc[i][j] += qv[i] * kv[j];
        }

        const float scale = 0.17677669529663687f;
#pragma unroll
        for (int i = 0; i < 3; i++) {
            float* sp = &g_sc[set][((size_t)(b*EE + q0 + i)*HH + h)*MM + m0];
#pragma unroll
            for (int j = 0; j < 6; j++) sp[j] = acc[i][j] * scale;
        }
    }
}

// ---------------- combine v3: 512 threads, 3 q per warp, low regs ----------------
__global__ __launch_bounds__(512) void k_combine(
    const float* __restrict__ ent,
    const float* __restrict__ b1, const float* __restrict__ ln1,
    const float* __restrict__ b2, const float* __restrict__ ln2,
    float* __restrict__ out)
{
    int e = blockIdx.x, b = blockIdx.y, set = blockIdx.z;
    int tid = threadIdx.x, lane = tid & 31, wid = tid >> 5;

    __shared__ int   ml[MAXML];
    __shared__ union {
        float scs[EE*HH][SCAP];
        struct { float mxs[EE*HH]; float ise[EE*HH]; float alpha[EE*HH*IC]; } sl;
    } u;
    __shared__ float Vs[IC*HH][DD];

    int cnt = g_mcnt[b*EE + e];
    if (tid < MAXML) ml[tid] = (tid < cnt) ? g_mlist[(b*EE + e)*MAXML + tid] : 0;
    __syncthreads();

    const float* scb = g_sc[set] + (size_t)b*EE*HH*MM;
    bool fast = (cnt <= SCAP);

    if (fast) {
        for (int idx = tid; idx < EE*HH*cnt; idx += 512) {
            int qh = idx / cnt, i = idx - qh*cnt;
            u.scs[qh][i] = scb[qh*MM + ml[i]];
        }
        __syncthreads();
        for (int t = tid; t < EE*HH; t += 512) {
            float mx = -1e30f;
#pragma unroll
            for (int i = 0; i < SCAP; i++) if (i < cnt) mx = fmaxf(mx, u.scs[t][i]);
            float s = 0.f;
#pragma unroll
            for (int i = 0; i < SCAP; i++) if (i < cnt) s += __expf(u.scs[t][i] - mx);
            float inv = 1.f / s;
#pragma unroll
            for (int i = 0; i < SCAP; i++) if (i < cnt) u.scs[t][i] = __expf(u.scs[t][i] - mx) * inv;
        }
    } else {
        for (int t = tid; t < EE*HH; t += 512) {
            const float* sp = scb + t*MM;
            float mx = -1e30f;
            for (int i = 0; i < cnt; i++) mx = fmaxf(mx, sp[ml[i]]);
            float s = 0.f;
            for (int i = 0; i < cnt; i++) s += __expf(sp[ml[i]] - mx);
            u.sl.mxs[t] = mx; u.sl.ise[t] = 1.f / s;
        }
    }

    int d0 = lane*4, d1 = 128 + lane*4;
    float acc[3][8];
#pragma unroll
    for (int t = 0; t < 3; t++)
#pragma unroll
        for (int j = 0; j < 8; j++) acc[t][j] = 0.f;

    __syncthreads();

    const float* vohb = g_voh[set] + ((size_t)b*MM)*HH*DD;

    for (int ic0 = 0; ic0 < cnt; ic0 += IC) {
        int icn = min(IC, cnt - ic0);
        int rows = icn * HH;
        for (int idx = tid; idx < rows*64; idx += 512) {
            int rr = idx >> 6, dq = (idx & 63) * 4;
            int ii = rr >> 3, h = rr & 7;
            int m = ml[ic0 + ii];
            *(float4*)&Vs[rr][dq] = *(const float4*)(vohb + ((size_t)m*HH + h)*DD + dq);
        }
        if (!fast) {
            for (int t = tid; t < EE*HH*icn; t += 512) {
                int qh = t / icn, ii = t - qh*icn;
                float sv = scb[qh*MM + ml[ic0 + ii]];
                u.sl.alpha[qh*IC + ii] = __expf(sv - u.sl.mxs[qh]) * u.sl.ise[qh];
            }
        }
        __syncthreads();

        for (int p = 0; p < rows; p++) {
            int ii = p >> 3, h = p & 7;
            float4 v0 = *(float4*)&Vs[p][d0];
            float4 v1 = *(float4*)&Vs[p][d1];
#pragma unroll
            for (int t = 0; t < 3; t++) {
                int q = wid + 16*t;
                float a = fast ? u.scs[q*HH + h][ic0 + ii]
                               : u.sl.alpha[(q*HH + h)*IC + ii];
                acc[t][0] += a*v0.x; acc[t][1] += a*v0.y;
                acc[t][2] += a*v0.z; acc[t][3] += a*v0.w;
                acc[t][4] += a*v1.x; acc[t][5] += a*v1.y;
                acc[t][6] += a*v1.z; acc[t][7] += a*v1.w;
            }
        }
        __syncthreads();
    }

    // epilogue: constants loaded here (keeps mainloop register pressure low)
    const float* bbp = (set ? b2 : b1) + 3*DD;
    const float* ln  = (set ? ln2 : ln1);
    float4 bo0 = *(const float4*)(bbp + d0),      bo1 = *(const float4*)(bbp + d1);
    float4 gm0 = *(const float4*)(ln + d0),       gm1 = *(const float4*)(ln + d1);
    float4 bt0 = *(const float4*)(ln + DD + d0),  bt1 = *(const float4*)(ln + DD + d1);

#pragma unroll
    for (int t = 0; t < 3; t++) {
        int q = wid + 16*t;
        const float* er = ent + (size_t)(b*EE + q)*DD;
        float4 e0 = *(const float4*)(er + d0);
        float4 e1 = *(const float4*)(er + d1);
        float x[8];
        x[0] = acc[t][0] + bo0.x + e0.x; x[1] = acc[t][1] + bo0.y + e0.y;
        x[2] = acc[t][2] + bo0.z + e0.z; x[3] = acc[t][3] + bo0.w + e0.w;
        x[4] = acc[t][4] + bo1.x + e1.x; x[5] = acc[t][5] + bo1.y + e1.y;
        x[6] = acc[t][6] + bo1.z + e1.z; x[7] = acc[t][7] + bo1.w + e1.w;
        float sm = 0.f;
#pragma unroll
        for (int j = 0; j < 8; j++) sm += x[j];
#pragma unroll
        for (int o = 16; o > 0; o >>= 1) sm += __shfl_xor_sync(0xffffffffu, sm, o);
        float mu = sm * (1.f/DD);
        float vv = 0.f;
#pragma unroll
        for (int j = 0; j < 8; j++) { x[j] -= mu; vv += x[j]*x[j]; }
#pragma unroll
        for (int o = 16; o > 0; o >>= 1) vv += __shfl_xor_sync(0xffffffffu, vv, o);
        float rs = rsqrtf(vv*(1.f/DD) + 1e-5f);

        int orow = set ? (q*EE + e) : (e*EE + q);
        float* op = out + ((size_t)set*BB*PAIRS + (size_t)b*PAIRS + orow)*DD;
        float4 o0, o1;
        o0.x = x[0]*rs*gm0.x + bt0.x; o0.y = x[1]*rs*gm0.y + bt0.y;
        o0.z = x[2]*rs*gm0.z + bt0.z; o0.w = x[3]*rs*gm0.w + bt0.w;
        o1.x = x[4]*rs*gm1.x + bt1.x; o1.y = x[5]*rs*gm1.y + bt1.y;
        o1.z = x[6]*rs*gm1.z + bt1.z; o1.w = x[7]*rs*gm1.w + bt1.w;
        *(float4*)(op + d0) = o0;
        *(float4*)(op + d1) = o1;
    }
}

// ---------------- launch ----------------
extern "C" void kernel_launch(void* const* d_in, const int* in_sizes, int n_in,
                              void* d_out, int out_size) {
    const void*  info = d_in[0];
    const float* ent  = (const float*)d_in[2];
    const float* men  = (const float*)d_in[3];
    const float* sen  = (const float*)d_in[4];
    const float* W1   = (const float*)d_in[5];
    const float* b1   = (const float*)d_in[6];
    const float* ln1  = (const float*)d_in[7];
    const float* W2   = (const float*)d_in[8];
    const float* b2   = (const float*)d_in[9];
    const float* ln2  = (const float*)d_in[10];
    float* out = (float*)d_out;

    k_prep<<<BB, 128>>>(info);
    k_proj_all<<<240, 256>>>(ent, men, sen, W1, b1, W2, b2);
    k_vs<<<1280, 256>>>(W1, W2);
    k_combine<<<dim3(EE, BB, 2), 512>>>(ent, b1, ln1, b2, ln2, out);
}

// round 7
// speedup vs baseline: 3.3691x; 1.0521x over previous
#include <cuda_runtime.h>

#define BB   32
#define EE   48
#define MM   96
#define DD   256
#define HH   8
#define DPH  32
#define PAIRS (EE*EE)
#define MAXML 64
#define IC   4
#define SCAP 8

// ---------------- scratch ----------------
__device__ int   g_sidx[BB*MM];
__device__ int   g_mlist[BB*EE*MAXML];
__device__ int   g_mcnt [BB*EE];
__device__ float g_qp [2][BB*EE*DD];
__device__ float g_kp [2][BB*MM*DD];
__device__ float g_v  [2][BB*MM*DD];
__device__ float g_voh[2][BB*MM*HH*DD];
__device__ float g_sc [2][BB*EE*HH*MM];

__device__ __forceinline__ void fma2(float2& d, float2 a, float2 b) {
    unsigned long long dd = *(unsigned long long*)&d;
    unsigned long long aa = *(unsigned long long*)&a;
    unsigned long long bb = *(unsigned long long*)&b;
    asm("fma.rn.f32x2 %0, %1, %2, %0;" : "+l"(dd) : "l"(aa), "l"(bb));
    d = *(float2*)&dd;
}

// ---------------- prep: one block per doc ----------------
__global__ void k_prep(const void* info) {
    int b = blockIdx.x, tid = threadIdx.x;
    __shared__ int smid[MM];
    __shared__ int s[128];
    const int* p32 = (const int*)info;
    int mx = 0;
    for (int r = tid; r < BB*MM; r += 128) mx = max(mx, p32[r*6 + 4]);
    s[tid] = mx; __syncthreads();
    for (int o = 64; o > 0; o >>= 1) { if (tid < o) s[tid] = max(s[tid], s[tid+o]); __syncthreads(); }
    int is32 = (s[0] > 0);
    for (int m = tid; m < MM; m += 128) {
        int r = b*MM + m;
        int e, sidx;
        if (is32) { e = p32[r*6 + 0]; sidx = p32[r*6 + 4]; }
        else {
            const long long* p64 = (const long long*)info;
            e = (int)p64[r*6 + 0]; sidx = (int)p64[r*6 + 4];
        }
        smid[m] = e; g_sidx[r] = sidx;
    }
    __syncthreads();
    for (int e = tid; e < EE; e += 128) {
        int target = b*EE + e;
        int cnt = 0;
        for (int m = 0; m < MM; m++) {
            if (smid[m] == target && cnt < MAXML)
                g_mlist[target*MAXML + cnt++] = m;
        }
        g_mcnt[target] = cnt;
    }
}

// ---------------- all 6 projections: 128x128 tiles, KSTEP=16, f32x2 ----------------
__global__ __launch_bounds__(256, 2) void k_proj_all(
    const float* __restrict__ ent, const float* __restrict__ men, const float* __restrict__ sen,
    const float* __restrict__ W1, const float* __restrict__ b1,
    const float* __restrict__ W2, const float* __restrict__ b2)
{
    __shared__ float2 As2[16][128];
    __shared__ float2 Ws2[16][64];

    int blk = blockIdx.x;
    int cb = blk & 1, rb = blk >> 1;
    int set = rb / 60; int r = rb % 60;
    const float* A; int gather = 0, type, row0;
    if (r < 12)      { type = 0; row0 = r*128;      A = ent; }
    else if (r < 36) { type = 1; row0 = (r-12)*128; A = sen; gather = 1; }
    else             { type = 2; row0 = (r-36)*128; A = men; }
    const float* W  = (set ? W2 : W1) + type*DD*DD;
    const float* bi = (set ? b2 : b1) + type*DD;
    float* C = (type == 0) ? g_qp[set] : (type == 1 ? g_kp[set] : g_v[set]);
    int n0 = cb*128;

    int tid = threadIdx.x;
    int tx = tid & 15, ty = tid >> 4;

    int am  = tid >> 1;
    int akq = (tid & 1) * 8;
    int arow = row0 + am;
    int asrc = gather ? g_sidx[arow] : arow;
    const float* aptr = A + (size_t)asrc*DD + akq;
    int wk = tid >> 4;
    int wn = (tid & 15) * 8;
    const float* wptr = W + (size_t)wk*DD + n0 + wn;
    int wp = (tid & 15) * 4;

    float2 acc2[8][4];
#pragma unroll
    for (int i = 0; i < 8; i++)
#pragma unroll
        for (int j = 0; j < 4; j++) acc2[i][j] = make_float2(0.f, 0.f);

    for (int k0 = 0; k0 < DD; k0 += 16) {
        float4 a0 = *(const float4*)(aptr + k0);
        float4 a1 = *(const float4*)(aptr + k0 + 4);
        float4 w0 = *(const float4*)(wptr + (size_t)k0*DD);
        float4 w1 = *(const float4*)(wptr + (size_t)k0*DD + 4);
        As2[akq+0][am] = make_float2(a0.x, a0.x);
        As2[akq+1][am] = make_float2(a0.y, a0.y);
        As2[akq+2][am] = make_float2(a0.z, a0.z);
        As2[akq+3][am] = make_float2(a0.w, a0.w);
        As2[akq+4][am] = make_float2(a1.x, a1.x);
        As2[akq+5][am] = make_float2(a1.y, a1.y);
        As2[akq+6][am] = make_float2(a1.z, a1.z);
        As2[akq+7][am] = make_float2(a1.w, a1.w);
        Ws2[wk][wp]   = make_float2(w0.x, w0.y);
        Ws2[wk][wp+1] = make_float2(w0.z, w0.w);
        Ws2[wk][wp+2] = make_float2(w1.x, w1.y);
        Ws2[wk][wp+3] = make_float2(w1.z, w1.w);
        __syncthreads();
#pragma unroll
        for (int kk = 0; kk < 16; kk++) {
            float2 a[8], bfr[4];
#pragma unroll
            for (int i = 0; i < 8; i++) a[i] = As2[kk][ty*8 + i];
#pragma unroll
            for (int j = 0; j < 4; j++) bfr[j] = Ws2[kk][tx*4 + j];
#pragma unroll
            for (int i = 0; i < 8; i++)
#pragma unroll
                for (int j = 0; j < 4; j++) fma2(acc2[i][j], a[i], bfr[j]);
        }
        __syncthreads();
    }

    float bj[8];
#pragma unroll
    for (int j = 0; j < 8; j++) bj[j] = bi[n0 + tx*8 + j];
#pragma unroll
    for (int i = 0; i < 8; i++) {
        int row = row0 + ty*8 + i;
        float* crow = C + (size_t)row*DD + n0 + tx*8;
        float4 o0, o1;
        o0.x = acc2[i][0].x+bj[0]; o0.y = acc2[i][0].y+bj[1];
        o0.z = acc2[i][1].x+bj[2]; o0.w = acc2[i][1].y+bj[3];
        o1.x = acc2[i][2].x+bj[4]; o1.y = acc2[i][2].y+bj[5];
        o1.z = acc2[i][3].x+bj[6]; o1.w = acc2[i][3].y+bj[7];
        *(float4*)crow       = o0;
        *(float4*)(crow + 4) = o1;
    }
}

// ---------------- fused voh (blocks 0..767) + scores (blocks 768..1279) ----------------
struct SmemVoh { float2 As2[32][128]; float2 Ws2[32][64]; };
struct SmemSc  { float qh[32][48]; float kh[32][96]; };

__global__ __launch_bounds__(256) void k_vs(const float* __restrict__ W1, const float* __restrict__ W2) {
    __shared__ union { SmemVoh v; SmemSc s; } sm;
    int bx = blockIdx.x;
    int tid = threadIdx.x;

    if (bx < 768) {
        int x = bx % 24, rest = bx / 24;
        int y = rest & 1, z = rest >> 1;
        int set = z >> 3, h = z & 7;
        const float* Wout = (set ? W2 : W1) + 3*DD*DD + h*DPH*DD;
        const float* V = g_v[set];
        int r0 = x * 128, n0 = y * 128;
        int tx = tid & 15, ty = tid >> 4;

        {
            int rr = tid >> 1, kq = (tid & 1) * 16;
            const float* ap = V + (size_t)(r0 + rr)*DD + h*DPH + kq;
#pragma unroll
            for (int c = 0; c < 4; c++) {
                float4 av = *(const float4*)(ap + c*4);
                sm.v.As2[kq + c*4 + 0][rr] = make_float2(av.x, av.x);
                sm.v.As2[kq + c*4 + 1][rr] = make_float2(av.y, av.y);
                sm.v.As2[kq + c*4 + 2][rr] = make_float2(av.z, av.z);
                sm.v.As2[kq + c*4 + 3][rr] = make_float2(av.w, av.w);
            }
        }
        {
            int wk = tid >> 5, wp = (tid & 31) * 2, wn = (tid & 31) * 4;
#pragma unroll
            for (int s = 0; s < 4; s++) {
                float4 wv = *(const float4*)(Wout + (size_t)(wk + 8*s)*DD + n0 + wn);
                sm.v.Ws2[wk + 8*s][wp]   = make_float2(wv.x, wv.y);
                sm.v.Ws2[wk + 8*s][wp+1] = make_float2(wv.z, wv.w);
            }
        }
        __syncthreads();

        float2 acc2[8][4];
#pragma unroll
        for (int i = 0; i < 8; i++)
#pragma unroll
            for (int j = 0; j < 4; j++) acc2[i][j] = make_float2(0.f, 0.f);

#pragma unroll
        for (int kk = 0; kk < 32; kk++) {
            float2 a[8], bfr[4];
#pragma unroll
            for (int i = 0; i < 8; i++) a[i] = sm.v.As2[kk][ty*8 + i];
#pragma unroll
            for (int j = 0; j < 4; j++) bfr[j] = sm.v.Ws2[kk][tx*4 + j];
#pragma unroll
            for (int i = 0; i < 8; i++)
#pragma unroll
                for (int j = 0; j < 4; j++) fma2(acc2[i][j], a[i], bfr[j]);
        }

#pragma unroll
        for (int i = 0; i < 8; i++) {
            int row = r0 + ty*8 + i;
            float* op = g_voh[set] + ((size_t)row*HH + h)*DD + n0 + tx*8;
            float4 o0, o1;
            o0.x = acc2[i][0].x; o0.y = acc2[i][0].y; o0.z = acc2[i][1].x; o0.w = acc2[i][1].y;
            o1.x = acc2[i][2].x; o1.y = acc2[i][2].y; o1.z = acc2[i][3].x; o1.w = acc2[i][3].y;
            *(float4*)op       = o0;
            *(float4*)(op + 4) = o1;
        }
    } else {
        int id = bx - 768;
        int h = id & 7, b = (id >> 3) & 31, set = id >> 8;

        for (int i = tid; i < EE*DPH; i += 256) {
            int q = i >> 5, d = i & 31;
            sm.s.qh[d][q] = g_qp[set][(b*EE + q)*DD + h*DPH + d];
        }
        for (int i = tid; i < MM*DPH; i += 256) {
            int m = i >> 5, d = i & 31;
            sm.s.kh[d][m] = g_kp[set][(b*MM + m)*DD + h*DPH + d];
        }
        __syncthreads();

        int q0 = (tid >> 4) * 3;
        int m0 = (tid & 15) * 6;
        float acc[3][6];
#pragma unroll
        for (int i = 0; i < 3; i++)
#pragma unroll
            for (int j = 0; j < 6; j++) acc[i][j] = 0.f;

#pragma unroll 8
        for (int kk = 0; kk < DPH; kk++) {
            float qv[3], kv[6];
#pragma unroll
            for (int i = 0; i < 3; i++) qv[i] = sm.s.qh[kk][q0 + i];
#pragma unroll
            for (int j = 0; j < 6; j++) kv[j] = sm.s.kh[kk][m0 + j];
#pragma unroll
            for (int i = 0; i < 3; i++)
#pragma unroll
                for (int j = 0; j < 6; j++) acc[i][j] += qv[i] * kv[j];
        }

        const float scale = 0.17677669529663687f;
#pragma unroll
        for (int i = 0; i < 3; i++) {
            float* sp = &g_sc[set][((size_t)(b*EE + q0 + i)*HH + h)*MM + m0];
#pragma unroll
            for (int j = 0; j < 6; j++) sp[j] = acc[i][j] * scale;
        }
    }
}

// LayerNorm + write helper (x[8] at d = d0..d0+3, d1..d1+3)
__device__ __forceinline__ void ln_write(
    float* x, const float* ln, float* op, int d0, int d1)
{
    float sm = 0.f;
#pragma unroll
    for (int j = 0; j < 8; j++) sm += x[j];
#pragma unroll
    for (int o = 16; o > 0; o >>= 1) sm += __shfl_xor_sync(0xffffffffu, sm, o);
    float mu = sm * (1.f/DD);
    float vv = 0.f;
#pragma unroll
    for (int j = 0; j < 8; j++) { x[j] -= mu; vv += x[j]*x[j]; }
#pragma unroll
    for (int o = 16; o > 0; o >>= 1) vv += __shfl_xor_sync(0xffffffffu, vv, o);
    float rs = rsqrtf(vv*(1.f/DD) + 1e-5f);

    float4 gm0 = *(const float4*)(ln + d0),      gm1 = *(const float4*)(ln + d1);
    float4 bt0 = *(const float4*)(ln + DD + d0), bt1 = *(const float4*)(ln + DD + d1);
    float4 o0, o1;
    o0.x = x[0]*rs*gm0.x + bt0.x; o0.y = x[1]*rs*gm0.y + bt0.y;
    o0.z = x[2]*rs*gm0.z + bt0.z; o0.w = x[3]*rs*gm0.w + bt0.w;
    o1.x = x[4]*rs*gm1.x + bt1.x; o1.y = x[5]*rs*gm1.y + bt1.y;
    o1.z = x[6]*rs*gm1.z + bt1.z; o1.w = x[7]*rs*gm1.w + bt1.w;
    *(float4*)(op + d0) = o0;
    *(float4*)(op + d1) = o1;
}

// ---------------- combine v4: cnt==1 fast path + f32x2 mainloop ----------------
__global__ __launch_bounds__(512) void k_combine(
    const float* __restrict__ ent,
    const float* __restrict__ b1, const float* __restrict__ ln1,
    const float* __restrict__ b2, const float* __restrict__ ln2,
    float* __restrict__ out)
{
    int e = blockIdx.x, b = blockIdx.y, set = blockIdx.z;
    int tid = threadIdx.x, lane = tid & 31, wid = tid >> 5;

    __shared__ int   ml[MAXML];
    __shared__ union {
        float scs[EE*HH][SCAP];
        struct { float mxs[EE*HH]; float ise[EE*HH]; float alpha[EE*HH*IC]; } sl;
    } u;
    __shared__ float Vs[IC*HH][DD];

    int cnt = g_mcnt[b*EE + e];
    if (tid < MAXML) ml[tid] = (tid < cnt) ? g_mlist[(b*EE + e)*MAXML + tid] : 0;
    __syncthreads();

    const float* vohb = g_voh[set] + (size_t)b*MM*HH*DD;
    const float* bbp  = (set ? b2 : b1) + 3*DD;
    const float* ln   = (set ? ln2 : ln1);
    int d0 = lane*4, d1 = 128 + lane*4;
    size_t outb = ((size_t)set*BB + b) * PAIRS * DD;

    if (cnt == 1) {
        // alphas are identically 1: out = bias + sum_h voh[m,h,:], same for all q
        int m = ml[0];
        {
            int rr = tid >> 6, dq = (tid & 63) * 4;
            *(float4*)&Vs[rr][dq] = *(const float4*)(vohb + ((size_t)m*HH + rr)*DD + dq);
        }
        __syncthreads();
        float4 bo0 = *(const float4*)(bbp + d0), bo1 = *(const float4*)(bbp + d1);
        float s[8];
        s[0]=bo0.x; s[1]=bo0.y; s[2]=bo0.z; s[3]=bo0.w;
        s[4]=bo1.x; s[5]=bo1.y; s[6]=bo1.z; s[7]=bo1.w;
#pragma unroll
        for (int h = 0; h < HH; h++) {
            float4 v0 = *(float4*)&Vs[h][d0];
            float4 v1 = *(float4*)&Vs[h][d1];
            s[0]+=v0.x; s[1]+=v0.y; s[2]+=v0.z; s[3]+=v0.w;
            s[4]+=v1.x; s[5]+=v1.y; s[6]+=v1.z; s[7]+=v1.w;
        }
#pragma unroll
        for (int t = 0; t < 3; t++) {
            int q = wid + 16*t;
            const float* er = ent + (size_t)(b*EE + q)*DD;
            float4 e0 = *(const float4*)(er + d0);
            float4 e1 = *(const float4*)(er + d1);
            float x[8];
            x[0]=s[0]+e0.x; x[1]=s[1]+e0.y; x[2]=s[2]+e0.z; x[3]=s[3]+e0.w;
            x[4]=s[4]+e1.x; x[5]=s[5]+e1.y; x[6]=s[6]+e1.z; x[7]=s[7]+e1.w;
            int orow = set ? (q*EE + e) : (e*EE + q);
            ln_write(x, ln, out + outb + (size_t)orow*DD, d0, d1);
        }
        return;
    }

    const float* scb = g_sc[set] + (size_t)b*EE*HH*MM;
    bool fast = (cnt <= SCAP);

    if (fast) {
        for (int idx = tid; idx < EE*HH*cnt; idx += 512) {
            int qh = idx / cnt, i = idx - qh*cnt;
            u.scs[qh][i] = scb[qh*MM + ml[i]];
        }
        __syncthreads();
        for (int t = tid; t < EE*HH; t += 512) {
            float mx = -1e30f;
#pragma unroll
            for (int i = 0; i < SCAP; i++) if (i < cnt) mx = fmaxf(mx, u.scs[t][i]);
            float s = 0.f;
#pragma unroll
            for (int i = 0; i < SCAP; i++) if (i < cnt) s += __expf(u.scs[t][i] - mx);
            float inv = 1.f / s;
#pragma unroll
            for (int i = 0; i < SCAP; i++) if (i < cnt) u.scs[t][i] = __expf(u.scs[t][i] - mx) * inv;
        }
    } else {
        for (int t = tid; t < EE*HH; t += 512) {
            const float* sp = scb + t*MM;
            float mx = -1e30f;
            for (int i = 0; i < cnt; i++) mx = fmaxf(mx, sp[ml[i]]);
            float s = 0.f;
            for (int i = 0; i < cnt; i++) s += __expf(sp[ml[i]] - mx);
            u.sl.mxs[t] = mx; u.sl.ise[t] = 1.f / s;
        }
    }

    float2 acc2[3][4];
#pragma unroll
    for (int t = 0; t < 3; t++)
#pragma unroll
        for (int j = 0; j < 4; j++) acc2[t][j] = make_float2(0.f, 0.f);

    __syncthreads();

    for (int ic0 = 0; ic0 < cnt; ic0 += IC) {
        int icn = min(IC, cnt - ic0);
        int rows = icn * HH;
        for (int idx = tid; idx < rows*64; idx += 512) {
            int rr = idx >> 6, dq = (idx & 63) * 4;
            int ii = rr >> 3, h = rr & 7;
            int m = ml[ic0 + ii];
            *(float4*)&Vs[rr][dq] = *(const float4*)(vohb + ((size_t)m*HH + h)*DD + dq);
        }
        if (!fast) {
            for (int t = tid; t < EE*HH*icn; t += 512) {
                int qh = t / icn, ii = t - qh*icn;
                float sv = scb[qh*MM + ml[ic0 + ii]];
                u.sl.alpha[qh*IC + ii] = __expf(sv - u.sl.mxs[qh]) * u.sl.ise[qh];
            }
        }
        __syncthreads();

        const float* vrow = Vs[0];
        for (int p = 0; p < rows; p++, vrow += DD) {
            int ii = p >> 3, h = p & 7;
            float2 v0a = *(const float2*)(vrow + d0);
            float2 v0b = *(const float2*)(vrow + d0 + 2);
            float2 v1a = *(const float2*)(vrow + d1);
            float2 v1b = *(const float2*)(vrow + d1 + 2);
#pragma unroll
            for (int t = 0; t < 3; t++) {
                int q = wid + 16*t;
                float a = fast ? u.scs[q*HH + h][ic0 + ii]
                               : u.sl.alpha[(q*HH + h)*IC + ii];
                float2 aa = make_float2(a, a);
                fma2(acc2[t][0], aa, v0a);
                fma2(acc2[t][1], aa, v0b);
                fma2(acc2[t][2], aa, v1a);
                fma2(acc2[t][3], aa, v1b);
            }
        }
        __syncthreads();
    }

    float4 bo0 = *(const float4*)(bbp + d0), bo1 = *(const float4*)(bbp + d1);
#pragma unroll
    for (int t = 0; t < 3; t++) {
        int q = wid + 16*t;
        const float* er = ent + (size_t)(b*EE + q)*DD;
        float4 e0 = *(const float4*)(er + d0);
        float4 e1 = *(const float4*)(er + d1);
        float x[8];
        x[0] = acc2[t][0].x + bo0.x + e0.x; x[1] = acc2[t][0].y + bo0.y + e0.y;
        x[2] = acc2[t][1].x + bo0.z + e0.z; x[3] = acc2[t][1].y + bo0.w + e0.w;
        x[4] = acc2[t][2].x + bo1.x + e1.x; x[5] = acc2[t][2].y + bo1.y + e1.y;
        x[6] = acc2[t][3].x + bo1.z + e1.z; x[7] = acc2[t][3].y + bo1.w + e1.w;
        int orow = set ? (q*EE + e) : (e*EE + q);
        ln_write(x, ln, out + outb + (size_t)orow*DD, d0, d1);
    }
}

// ---------------- launch ----------------
extern "C" void kernel_launch(void* const* d_in, const int* in_sizes, int n_in,
                              void* d_out, int out_size) {
    const void*  info = d_in[0];
    const float* ent  = (const float*)d_in[2];
    const float* men  = (const float*)d_in[3];
    const float* sen  = (const float*)d_in[4];
    const float* W1   = (const float*)d_in[5];
    const float* b1   = (const float*)d_in[6];
    const float* ln1  = (const float*)d_in[7];
    const float* W2   = (const float*)d_in[8];
    const float* b2   = (const float*)d_in[9];
    const float* ln2  = (const float*)d_in[10];
    float* out = (float*)d_out;

    k_prep<<<BB, 128>>>(info);
    k_proj_all<<<240, 256>>>(ent, men, sen, W1, b1, W2, b2);
    k_vs<<<1280, 256>>>(W1, W2);
    k_combine<<<dim3(EE, BB, 2), 512>>>(ent, b1, ln1, b2, ln2, out);
}

// round 8
// speedup vs baseline: 3.4529x; 1.0249x over previous
#include <cuda_runtime.h>

#define BB   32
#define EE   48
#define MM   96
#define DD   256
#define HH   8
#define DPH  32
#define PAIRS (EE*EE)
#define MAXML 64
#define IC   4
#define SCAP 8
#define QH   24   // q rows per combine block (half of EE)

// ---------------- scratch ----------------
__device__ int   g_sidx[BB*MM];
__device__ int   g_mlist[BB*EE*MAXML];
__device__ int   g_mcnt [BB*EE];
__device__ float g_qp [2][BB*EE*DD];
__device__ float g_kp [2][BB*MM*DD];
__device__ float g_v  [2][BB*MM*DD];
__device__ float g_voh[2][BB*MM*HH*DD];
__device__ float g_sc [2][BB*EE*HH*MM];

__device__ __forceinline__ void fma2(float2& d, float2 a, float2 b) {
    unsigned long long dd = *(unsigned long long*)&d;
    unsigned long long aa = *(unsigned long long*)&a;
    unsigned long long bb = *(unsigned long long*)&b;
    asm("fma.rn.f32x2 %0, %1, %2, %0;" : "+l"(dd) : "l"(aa), "l"(bb));
    d = *(float2*)&dd;
}

// ---------------- prep: one block per doc ----------------
__global__ void k_prep(const void* info) {
    int b = blockIdx.x, tid = threadIdx.x;
    __shared__ int smid[MM];
    __shared__ int s[128];
    const int* p32 = (const int*)info;
    int mx = 0;
    for (int r = tid; r < BB*MM; r += 128) mx = max(mx, p32[r*6 + 4]);
    s[tid] = mx; __syncthreads();
    for (int o = 64; o > 0; o >>= 1) { if (tid < o) s[tid] = max(s[tid], s[tid+o]); __syncthreads(); }
    int is32 = (s[0] > 0);
    for (int m = tid; m < MM; m += 128) {
        int r = b*MM + m;
        int e, sidx;
        if (is32) { e = p32[r*6 + 0]; sidx = p32[r*6 + 4]; }
        else {
            const long long* p64 = (const long long*)info;
            e = (int)p64[r*6 + 0]; sidx = (int)p64[r*6 + 4];
        }
        smid[m] = e; g_sidx[r] = sidx;
    }
    __syncthreads();
    for (int e = tid; e < EE; e += 128) {
        int target = b*EE + e;
        int cnt = 0;
        for (int m = 0; m < MM; m++) {
            if (smid[m] == target && cnt < MAXML)
                g_mlist[target*MAXML + cnt++] = m;
        }
        g_mcnt[target] = cnt;
    }
}

// ---------------- all 6 projections: 128x128 tiles, KSTEP=16, f32x2 ----------------
__global__ __launch_bounds__(256, 2) void k_proj_all(
    const float* __restrict__ ent, const float* __restrict__ men, const float* __restrict__ sen,
    const float* __restrict__ W1, const float* __restrict__ b1,
    const float* __restrict__ W2, const float* __restrict__ b2)
{
    __shared__ float2 As2[16][128];
    __shared__ float2 Ws2[16][64];

    int blk = blockIdx.x;
    int cb = blk & 1, rb = blk >> 1;
    int set = rb / 60; int r = rb % 60;
    const float* A; int gather = 0, type, row0;
    if (r < 12)      { type = 0; row0 = r*128;      A = ent; }
    else if (r < 36) { type = 1; row0 = (r-12)*128; A = sen; gather = 1; }
    else             { type = 2; row0 = (r-36)*128; A = men; }
    const float* W  = (set ? W2 : W1) + type*DD*DD;
    const float* bi = (set ? b2 : b1) + type*DD;
    float* C = (type == 0) ? g_qp[set] : (type == 1 ? g_kp[set] : g_v[set]);
    int n0 = cb*128;

    int tid = threadIdx.x;
    int tx = tid & 15, ty = tid >> 4;

    int am  = tid >> 1;
    int akq = (tid & 1) * 8;
    int arow = row0 + am;
    int asrc = gather ? g_sidx[arow] : arow;
    const float* aptr = A + (size_t)asrc*DD + akq;
    int wk = tid >> 4;
    int wn = (tid & 15) * 8;
    const float* wptr = W + (size_t)wk*DD + n0 + wn;
    int wp = (tid & 15) * 4;

    float2 acc2[8][4];
#pragma unroll
    for (int i = 0; i < 8; i++)
#pragma unroll
        for (int j = 0; j < 4; j++) acc2[i][j] = make_float2(0.f, 0.f);

    for (int k0 = 0; k0 < DD; k0 += 16) {
        float4 a0 = *(const float4*)(aptr + k0);
        float4 a1 = *(const float4*)(aptr + k0 + 4);
        float4 w0 = *(const float4*)(wptr + (size_t)k0*DD);
        float4 w1 = *(const float4*)(wptr + (size_t)k0*DD + 4);
        As2[akq+0][am] = make_float2(a0.x, a0.x);
        As2[akq+1][am] = make_float2(a0.y, a0.y);
        As2[akq+2][am] = make_float2(a0.z, a0.z);
        As2[akq+3][am] = make_float2(a0.w, a0.w);
        As2[akq+4][am] = make_float2(a1.x, a1.x);
        As2[akq+5][am] = make_float2(a1.y, a1.y);
        As2[akq+6][am] = make_float2(a1.z, a1.z);
        As2[akq+7][am] = make_float2(a1.w, a1.w);
        Ws2[wk][wp]   = make_float2(w0.x, w0.y);
        Ws2[wk][wp+1] = make_float2(w0.z, w0.w);
        Ws2[wk][wp+2] = make_float2(w1.x, w1.y);
        Ws2[wk][wp+3] = make_float2(w1.z, w1.w);
        __syncthreads();
#pragma unroll
        for (int kk = 0; kk < 16; kk++) {
            float2 a[8], bfr[4];
#pragma unroll
            for (int i = 0; i < 8; i++) a[i] = As2[kk][ty*8 + i];
#pragma unroll
            for (int j = 0; j < 4; j++) bfr[j] = Ws2[kk][tx*4 + j];
#pragma unroll
            for (int i = 0; i < 8; i++)
#pragma unroll
                for (int j = 0; j < 4; j++) fma2(acc2[i][j], a[i], bfr[j]);
        }
        __syncthreads();
    }

    float bj[8];
#pragma unroll
    for (int j = 0; j < 8; j++) bj[j] = bi[n0 + tx*8 + j];
#pragma unroll
    for (int i = 0; i < 8; i++) {
        int row = row0 + ty*8 + i;
        float* crow = C + (size_t)row*DD + n0 + tx*8;
        float4 o0, o1;
        o0.x = acc2[i][0].x+bj[0]; o0.y = acc2[i][0].y+bj[1];
        o0.z = acc2[i][1].x+bj[2]; o0.w = acc2[i][1].y+bj[3];
        o1.x = acc2[i][2].x+bj[4]; o1.y = acc2[i][2].y+bj[5];
        o1.z = acc2[i][3].x+bj[6]; o1.w = acc2[i][3].y+bj[7];
        *(float4*)crow       = o0;
        *(float4*)(crow + 4) = o1;
    }
}

// ---------------- fused voh (blocks 0..767) + scores (blocks 768..1279) ----------------
struct SmemVoh { float2 As2[32][128]; float2 Ws2[32][64]; };
struct SmemSc  { float qh[32][48]; float kh[32][96]; };

__global__ __launch_bounds__(256) void k_vs(const float* __restrict__ W1, const float* __restrict__ W2) {
    __shared__ union { SmemVoh v; SmemSc s; } sm;
    int bx = blockIdx.x;
    int tid = threadIdx.x;

    if (bx < 768) {
        int x = bx % 24, rest = bx / 24;
        int y = rest & 1, z = rest >> 1;
        int set = z >> 3, h = z & 7;
        const float* Wout = (set ? W2 : W1) + 3*DD*DD + h*DPH*DD;
        const float* V = g_v[set];
        int r0 = x * 128, n0 = y * 128;
        int tx = tid & 15, ty = tid >> 4;

        {
            int rr = tid >> 1, kq = (tid & 1) * 16;
            const float* ap = V + (size_t)(r0 + rr)*DD + h*DPH + kq;
#pragma unroll
            for (int c = 0; c < 4; c++) {
                float4 av = *(const float4*)(ap + c*4);
                sm.v.As2[kq + c*4 + 0][rr] = make_float2(av.x, av.x);
                sm.v.As2[kq + c*4 + 1][rr] = make_float2(av.y, av.y);
                sm.v.As2[kq + c*4 + 2][rr] = make_float2(av.z, av.z);
                sm.v.As2[kq + c*4 + 3][rr] = make_float2(av.w, av.w);
            }
        }
        {
            int wk = tid >> 5, wp = (tid & 31) * 2, wn = (tid & 31) * 4;
#pragma unroll
            for (int s = 0; s < 4; s++) {
                float4 wv = *(const float4*)(Wout + (size_t)(wk + 8*s)*DD + n0 + wn);
                sm.v.Ws2[wk + 8*s][wp]   = make_float2(wv.x, wv.y);
                sm.v.Ws2[wk + 8*s][wp+1] = make_float2(wv.z, wv.w);
            }
        }
        __syncthreads();

        float2 acc2[8][4];
#pragma unroll
        for (int i = 0; i < 8; i++)
#pragma unroll
            for (int j = 0; j < 4; j++) acc2[i][j] = make_float2(0.f, 0.f);

#pragma unroll
        for (int kk = 0; kk < 32; kk++) {
            float2 a[8], bfr[4];
#pragma unroll
            for (int i = 0; i < 8; i++) a[i] = sm.v.As2[kk][ty*8 + i];
#pragma unroll
            for (int j = 0; j < 4; j++) bfr[j] = sm.v.Ws2[kk][tx*4 + j];
#pragma unroll
            for (int i = 0; i < 8; i++)
#pragma unroll
                for (int j = 0; j < 4; j++) fma2(acc2[i][j], a[i], bfr[j]);
        }

#pragma unroll
        for (int i = 0; i < 8; i++) {
            int row = r0 + ty*8 + i;
            float* op = g_voh[set] + ((size_t)row*HH + h)*DD + n0 + tx*8;
            float4 o0, o1;
            o0.x = acc2[i][0].x; o0.y = acc2[i][0].y; o0.z = acc2[i][1].x; o0.w = acc2[i][1].y;
            o1.x = acc2[i][2].x; o1.y = acc2[i][2].y; o1.z = acc2[i][3].x; o1.w = acc2[i][3].y;
            *(float4*)op       = o0;
            *(float4*)(op + 4) = o1;
        }
    } else {
        int id = bx - 768;
        int h = id & 7, b = (id >> 3) & 31, set = id >> 8;

        for (int i = tid; i < EE*DPH; i += 256) {
            int q = i >> 5, d = i & 31;
            sm.s.qh[d][q] = g_qp[set][(b*EE + q)*DD + h*DPH + d];
        }
        for (int i = tid; i < MM*DPH; i += 256) {
            int m = i >> 5, d = i & 31;
            sm.s.kh[d][m] = g_kp[set][(b*MM + m)*DD + h*DPH + d];
        }
        __syncthreads();

        int q0 = (tid >> 4) * 3;
        int m0 = (tid & 15) * 6;
        float acc[3][6];
#pragma unroll
        for (int i = 0; i < 3; i++)
#pragma unroll
            for (int j = 0; j < 6; j++) acc[i][j] = 0.f;

#pragma unroll 8
        for (int kk = 0; kk < DPH; kk++) {
            float qv[3], kv[6];
#pragma unroll
            for (int i = 0; i < 3; i++) qv[i] = sm.s.qh[kk][q0 + i];
#pragma unroll
            for (int j = 0; j < 6; j++) kv[j] = sm.s.kh[kk][m0 + j];
#pragma unroll
            for (int i = 0; i < 3; i++)
#pragma unroll
                for (int j = 0; j < 6; j++) acc[i][j] += qv[i] * kv[j];
        }

        const float scale = 0.17677669529663687f;
#pragma unroll
        for (int i = 0; i < 3; i++) {
            float* sp = &g_sc[set][((size_t)(b*EE + q0 + i)*HH + h)*MM + m0];
#pragma unroll
            for (int j = 0; j < 6; j++) sp[j] = acc[i][j] * scale;
        }
    }
}

// LayerNorm + write helper
__device__ __forceinline__ void ln_write(
    float* x, const float* ln, float* op, int d0, int d1)
{
    float sm = 0.f;
#pragma unroll
    for (int j = 0; j < 8; j++) sm += x[j];
#pragma unroll
    for (int o = 16; o > 0; o >>= 1) sm += __shfl_xor_sync(0xffffffffu, sm, o);
    float mu = sm * (1.f/DD);
    float vv = 0.f;
#pragma unroll
    for (int j = 0; j < 8; j++) { x[j] -= mu; vv += x[j]*x[j]; }
#pragma unroll
    for (int o = 16; o > 0; o >>= 1) vv += __shfl_xor_sync(0xffffffffu, vv, o);
    float rs = rsqrtf(vv*(1.f/DD) + 1e-5f);

    float4 gm0 = *(const float4*)(ln + d0),      gm1 = *(const float4*)(ln + d1);
    float4 bt0 = *(const float4*)(ln + DD + d0), bt1 = *(const float4*)(ln + DD + d1);
    float4 o0, o1;
    o0.x = x[0]*rs*gm0.x + bt0.x; o0.y = x[1]*rs*gm0.y + bt0.y;
    o0.z = x[2]*rs*gm0.z + bt0.z; o0.w = x[3]*rs*gm0.w + bt0.w;
    o1.x = x[4]*rs*gm1.x + bt1.x; o1.y = x[5]*rs*gm1.y + bt1.y;
    o1.z = x[6]*rs*gm1.z + bt1.z; o1.w = x[7]*rs*gm1.w + bt1.w;
    *(float4*)(op + d0) = o0;
    *(float4*)(op + d1) = o1;
}

// ---------------- combine v5: 256 threads, q-halved blocks, reg alphas ----------------
__global__ __launch_bounds__(256) void k_combine(
    const float* __restrict__ ent,
    const float* __restrict__ b1, const float* __restrict__ ln1,
    const float* __restrict__ b2, const float* __restrict__ ln2,
    float* __restrict__ out)
{
    int e = blockIdx.x, b = blockIdx.y, z = blockIdx.z;
    int set = z >> 1, half = z & 1;
    int q0 = half * QH;
    int tid = threadIdx.x, lane = tid & 31, wid = tid >> 5;

    __shared__ int ml[MAXML];
    __shared__ union {
        struct { float al[SCAP][QH*HH]; } f;                      // fast: normalized alphas
        struct { float mxs[QH*HH]; float ise[QH*HH]; float alpha[IC][QH*HH]; } sl;
    } u;
    __shared__ float Vs[IC*HH][DD];

    int cnt = g_mcnt[b*EE + e];
    if (tid < MAXML) ml[tid] = (tid < cnt) ? g_mlist[(b*EE + e)*MAXML + tid] : 0;
    __syncthreads();

    const float* vohb = g_voh[set] + (size_t)b*MM*HH*DD;
    const float* bbp  = (set ? b2 : b1) + 3*DD;
    const float* ln   = (set ? ln2 : ln1);
    int d0 = lane*4, d1 = 128 + lane*4;
    size_t outb = ((size_t)set*BB + b) * PAIRS * DD;

    if (cnt == 1) {
        int m = ml[0];
        for (int idx = tid; idx < HH*64; idx += 256) {
            int rr = idx >> 6, dq = (idx & 63) * 4;
            *(float4*)&Vs[rr][dq] = *(const float4*)(vohb + ((size_t)m*HH + rr)*DD + dq);
        }
        __syncthreads();
        float4 bo0 = *(const float4*)(bbp + d0), bo1 = *(const float4*)(bbp + d1);
        float s[8];
        s[0]=bo0.x; s[1]=bo0.y; s[2]=bo0.z; s[3]=bo0.w;
        s[4]=bo1.x; s[5]=bo1.y; s[6]=bo1.z; s[7]=bo1.w;
#pragma unroll
        for (int h = 0; h < HH; h++) {
            float4 v0 = *(float4*)&Vs[h][d0];
            float4 v1 = *(float4*)&Vs[h][d1];
            s[0]+=v0.x; s[1]+=v0.y; s[2]+=v0.z; s[3]+=v0.w;
            s[4]+=v1.x; s[5]+=v1.y; s[6]+=v1.z; s[7]+=v1.w;
        }
#pragma unroll
        for (int t = 0; t < 3; t++) {
            int q = q0 + wid + 8*t;
            const float* er = ent + (size_t)(b*EE + q)*DD;
            float4 e0 = *(const float4*)(er + d0);
            float4 e1 = *(const float4*)(er + d1);
            float x[8];
            x[0]=s[0]+e0.x; x[1]=s[1]+e0.y; x[2]=s[2]+e0.z; x[3]=s[3]+e0.w;
            x[4]=s[4]+e1.x; x[5]=s[5]+e1.y; x[6]=s[6]+e1.z; x[7]=s[7]+e1.w;
            int orow = set ? (q*EE + e) : (e*EE + q);
            ln_write(x, ln, out + outb + (size_t)orow*DD, d0, d1);
        }
        return;
    }

    const float* scb = g_sc[set] + (size_t)b*EE*HH*MM;
    bool fast = (cnt <= SCAP);

    if (fast) {
        // one task per thread: (lq, h); exp computed once, rescaled in place
        if (tid < QH*HH) {
            int lq = tid >> 3, h = tid & 7;
            const float* sp = scb + ((size_t)(q0 + lq)*HH + h)*MM;
            float sv[SCAP];
            float mx = -1e30f;
            for (int i = 0; i < cnt; i++) { sv[i] = sp[ml[i]]; mx = fmaxf(mx, sv[i]); }
            float s = 0.f;
            for (int i = 0; i < cnt; i++) { sv[i] = __expf(sv[i] - mx); s += sv[i]; }
            float inv = 1.f / s;
            for (int i = 0; i < cnt; i++) u.f.al[i][tid] = sv[i] * inv;
        }
    } else {
        for (int t = tid; t < QH*HH; t += 256) {
            int lq = t >> 3, h = t & 7;
            const float* sp = scb + ((size_t)(q0 + lq)*HH + h)*MM;
            float mx = -1e30f;
            for (int i = 0; i < cnt; i++) mx = fmaxf(mx, sp[ml[i]]);
            float s = 0.f;
            for (int i = 0; i < cnt; i++) s += __expf(sp[ml[i]] - mx);
            u.sl.mxs[t] = mx; u.sl.ise[t] = 1.f / s;
        }
    }

    float2 acc2[3][4];
#pragma unroll
    for (int t = 0; t < 3; t++)
#pragma unroll
        for (int j = 0; j < 4; j++) acc2[t][j] = make_float2(0.f, 0.f);

    __syncthreads();

    for (int ic0 = 0; ic0 < cnt; ic0 += IC) {
        int icn = min(IC, cnt - ic0);
        int rows = icn * HH;
        for (int idx = tid; idx < rows*64; idx += 256) {
            int rr = idx >> 6, dq = (idx & 63) * 4;
            int ii = rr >> 3, h = rr & 7;
            int m = ml[ic0 + ii];
            *(float4*)&Vs[rr][dq] = *(const float4*)(vohb + ((size_t)m*HH + h)*DD + dq);
        }
        if (!fast) {
            for (int t = tid; t < QH*HH*icn; t += 256) {
                int ii = t / (QH*HH), lqh = t - ii*(QH*HH);
                int lq = lqh >> 3, h = lqh & 7;
                float sv = scb[((size_t)(q0 + lq)*HH + h)*MM + ml[ic0 + ii]];
                u.sl.alpha[ii][lqh] = __expf(sv - u.sl.mxs[lqh]) * u.sl.ise[lqh];
            }
        }
        __syncthreads();

        for (int ii = 0; ii < icn; ii++) {
            // alphas for this mention, 3 q's x 8 heads, loaded as vectors into regs
            const float* arow = fast ? u.f.al[ic0 + ii] : u.sl.alpha[ii];
            float as_[3][8];
#pragma unroll
            for (int t = 0; t < 3; t++) {
                int lq = wid + 8*t;
                float4 x0 = *(const float4*)&arow[lq*8];
                float4 x1 = *(const float4*)&arow[lq*8 + 4];
                as_[t][0]=x0.x; as_[t][1]=x0.y; as_[t][2]=x0.z; as_[t][3]=x0.w;
                as_[t][4]=x1.x; as_[t][5]=x1.y; as_[t][6]=x1.z; as_[t][7]=x1.w;
            }
            const float* vbase = Vs[ii*8];
#pragma unroll
            for (int h = 0; h < HH; h++) {
                const float* vrow = vbase + h*DD;
                float4 v0 = *(const float4*)(vrow + d0);
                float4 v1 = *(const float4*)(vrow + d1);
                float2 v0a = make_float2(v0.x, v0.y), v0b = make_float2(v0.z, v0.w);
                float2 v1a = make_float2(v1.x, v1.y), v1b = make_float2(v1.z, v1.w);
#pragma unroll
                for (int t = 0; t < 3; t++) {
                    float2 aa = make_float2(as_[t][h], as_[t][h]);
                    fma2(acc2[t][0], aa, v0a);
                    fma2(acc2[t][1], aa, v0b);
                    fma2(acc2[t][2], aa, v1a);
                    fma2(acc2[t][3], aa, v1b);
                }
            }
        }
        __syncthreads();
    }

    float4 bo0 = *(const float4*)(bbp + d0), bo1 = *(const float4*)(bbp + d1);
#pragma unroll
    for (int t = 0; t < 3; t++) {
        int q = q0 + wid + 8*t;
        const float* er = ent + (size_t)(b*EE + q)*DD;
        float4 e0 = *(const float4*)(er + d0);
        float4 e1 = *(const float4*)(er + d1);
        float x[8];
        x[0] = acc2[t][0].x + bo0.x + e0.x; x[1] = acc2[t][0].y + bo0.y + e0.y;
        x[2] = acc2[t][1].x + bo0.z + e0.z; x[3] = acc2[t][1].y + bo0.w + e0.w;
        x[4] = acc2[t][2].x + bo1.x + e1.x; x[5] = acc2[t][2].y + bo1.y + e1.y;
        x[6] = acc2[t][3].x + bo1.z + e1.z; x[7] = acc2[t][3].y + bo1.w + e1.w;
        int orow = set ? (q*EE + e) : (e*EE + q);
        ln_write(x, ln, out + outb + (size_t)orow*DD, d0, d1);
    }
}

// ---------------- launch ----------------
extern "C" void kernel_launch(void* const* d_in, const int* in_sizes, int n_in,
                              void* d_out, int out_size) {
    const void*  info = d_in[0];
    const float* ent  = (const float*)d_in[2];
    const float* men  = (const float*)d_in[3];
    const float* sen  = (const float*)d_in[4];
    const float* W1   = (const float*)d_in[5];
    const float* b1   = (const float*)d_in[6];
    const float* ln1  = (const float*)d_in[7];
    const float* W2   = (const float*)d_in[8];
    const float* b2   = (const float*)d_in[9];
    const float* ln2  = (const float*)d_in[10];
    float* out = (float*)d_out;

    k_prep<<<BB, 128>>>(info);
    k_proj_all<<<240, 256>>>(ent, men, sen, W1, b1, W2, b2);
    k_vs<<<1280, 256>>>(W1, W2);
    k_combine<<<dim3(EE, BB, 4), 256>>>(ent, b1, ln1, b2, ln2, out);
}

// round 9
// speedup vs baseline: 3.5847x; 1.0382x over previous
#include <cuda_runtime.h>

#define BB   32
#define EE   48
#define MM   96
#define DD   256
#define HH   8
#define DPH  32
#define PAIRS (EE*EE)
#define MAXML 64
#define SCAP 8
#define QH   24   // q rows per combine block

// ---------------- scratch ----------------
__device__ int   g_sidx[BB*MM];
__device__ int   g_mlist[BB*EE*MAXML];
__device__ int   g_mcnt [BB*EE];
__device__ float g_qp [2][BB*EE*DD];
__device__ float g_kp [2][BB*MM*DD];
__device__ float g_v  [2][BB*MM*DD];
__device__ float g_voh[2][BB*MM*HH*DD];
__device__ float g_sc [2][BB*EE*HH*MM];

__device__ __forceinline__ void fma2(float2& d, float2 a, float2 b) {
    unsigned long long dd = *(unsigned long long*)&d;
    unsigned long long aa = *(unsigned long long*)&a;
    unsigned long long bb = *(unsigned long long*)&b;
    asm("fma.rn.f32x2 %0, %1, %2, %0;" : "+l"(dd) : "l"(aa), "l"(bb));
    d = *(float2*)&dd;
}

__device__ __forceinline__ float4 ldg4(const float* p) {
    return __ldg((const float4*)p);
}

// ---------------- prep: one block per doc ----------------
__global__ void k_prep(const void* info) {
    int b = blockIdx.x, tid = threadIdx.x;
    __shared__ int smid[MM];
    __shared__ int s[128];
    const int* p32 = (const int*)info;
    int mx = 0;
    for (int r = tid; r < BB*MM; r += 128) mx = max(mx, p32[r*6 + 4]);
    s[tid] = mx; __syncthreads();
    for (int o = 64; o > 0; o >>= 1) { if (tid < o) s[tid] = max(s[tid], s[tid+o]); __syncthreads(); }
    int is32 = (s[0] > 0);
    for (int m = tid; m < MM; m += 128) {
        int r = b*MM + m;
        int e, sidx;
        if (is32) { e = p32[r*6 + 0]; sidx = p32[r*6 + 4]; }
        else {
            const long long* p64 = (const long long*)info;
            e = (int)p64[r*6 + 0]; sidx = (int)p64[r*6 + 4];
        }
        smid[m] = e; g_sidx[r] = sidx;
    }
    __syncthreads();
    for (int e = tid; e < EE; e += 128) {
        int target = b*EE + e;
        int cnt = 0;
        for (int m = 0; m < MM; m++) {
            if (smid[m] == target && cnt < MAXML)
                g_mlist[target*MAXML + cnt++] = m;
        }
        g_mcnt[target] = cnt;
    }
}

// ---------------- all 6 projections: 128x128 tiles, KSTEP=16, f32x2 ----------------
__global__ __launch_bounds__(256, 2) void k_proj_all(
    const float* __restrict__ ent, const float* __restrict__ men, const float* __restrict__ sen,
    const float* __restrict__ W1, const float* __restrict__ b1,
    const float* __restrict__ W2, const float* __restrict__ b2)
{
    __shared__ float2 As2[16][128];
    __shared__ float2 Ws2[16][64];

    int blk = blockIdx.x;
    int cb = blk & 1, rb = blk >> 1;
    int set = rb / 60; int r = rb % 60;
    const float* A; int gather = 0, type, row0;
    if (r < 12)      { type = 0; row0 = r*128;      A = ent; }
    else if (r < 36) { type = 1; row0 = (r-12)*128; A = sen; gather = 1; }
    else             { type = 2; row0 = (r-36)*128; A = men; }
    const float* W  = (set ? W2 : W1) + type*DD*DD;
    const float* bi = (set ? b2 : b1) + type*DD;
    float* C = (type == 0) ? g_qp[set] : (type == 1 ? g_kp[set] : g_v[set]);
    int n0 = cb*128;

    int tid = threadIdx.x;
    int tx = tid & 15, ty = tid >> 4;

    int am  = tid >> 1;
    int akq = (tid & 1) * 8;
    int arow = row0 + am;
    int asrc = gather ? g_sidx[arow] : arow;
    const float* aptr = A + (size_t)asrc*DD + akq;
    int wk = tid >> 4;
    int wn = (tid & 15) * 8;
    const float* wptr = W + (size_t)wk*DD + n0 + wn;
    int wp = (tid & 15) * 4;

    float2 acc2[8][4];
#pragma unroll
    for (int i = 0; i < 8; i++)
#pragma unroll
        for (int j = 0; j < 4; j++) acc2[i][j] = make_float2(0.f, 0.f);

    for (int k0 = 0; k0 < DD; k0 += 16) {
        float4 a0 = *(const float4*)(aptr + k0);
        float4 a1 = *(const float4*)(aptr + k0 + 4);
        float4 w0 = *(const float4*)(wptr + (size_t)k0*DD);
        float4 w1 = *(const float4*)(wptr + (size_t)k0*DD + 4);
        As2[akq+0][am] = make_float2(a0.x, a0.x);
        As2[akq+1][am] = make_float2(a0.y, a0.y);
        As2[akq+2][am] = make_float2(a0.z, a0.z);
        As2[akq+3][am] = make_float2(a0.w, a0.w);
        As2[akq+4][am] = make_float2(a1.x, a1.x);
        As2[akq+5][am] = make_float2(a1.y, a1.y);
        As2[akq+6][am] = make_float2(a1.z, a1.z);
        As2[akq+7][am] = make_float2(a1.w, a1.w);
        Ws2[wk][wp]   = make_float2(w0.x, w0.y);
        Ws2[wk][wp+1] = make_float2(w0.z, w0.w);
        Ws2[wk][wp+2] = make_float2(w1.x, w1.y);
        Ws2[wk][wp+3] = make_float2(w1.z, w1.w);
        __syncthreads();
#pragma unroll
        for (int kk = 0; kk < 16; kk++) {
            float2 a[8], bfr[4];
#pragma unroll
            for (int i = 0; i < 8; i++) a[i] = As2[kk][ty*8 + i];
#pragma unroll
            for (int j = 0; j < 4; j++) bfr[j] = Ws2[kk][tx*4 + j];
#pragma unroll
            for (int i = 0; i < 8; i++)
#pragma unroll
                for (int j = 0; j < 4; j++) fma2(acc2[i][j], a[i], bfr[j]);
        }
        __syncthreads();
    }

    float bj[8];
#pragma unroll
    for (int j = 0; j < 8; j++) bj[j] = bi[n0 + tx*8 + j];
#pragma unroll
    for (int i = 0; i < 8; i++) {
        int row = row0 + ty*8 + i;
        float* crow = C + (size_t)row*DD + n0 + tx*8;
        float4 o0, o1;
        o0.x = acc2[i][0].x+bj[0]; o0.y = acc2[i][0].y+bj[1];
        o0.z = acc2[i][1].x+bj[2]; o0.w = acc2[i][1].y+bj[3];
        o1.x = acc2[i][2].x+bj[4]; o1.y = acc2[i][2].y+bj[5];
        o1.z = acc2[i][3].x+bj[6]; o1.w = acc2[i][3].y+bj[7];
        *(float4*)crow       = o0;
        *(float4*)(crow + 4) = o1;
    }
}

// ---------------- fused voh (blocks 0..767) + scores (blocks 768..1279) ----------------
struct SmemVoh { float2 As2[32][128]; float2 Ws2[32][64]; };
struct SmemSc  { float qh[32][48]; float kh[32][96]; };

__global__ __launch_bounds__(256) void k_vs(const float* __restrict__ W1, const float* __restrict__ W2) {
    __shared__ union { SmemVoh v; SmemSc s; } sm;
    int bx = blockIdx.x;
    int tid = threadIdx.x;

    if (bx < 768) {
        int x = bx % 24, rest = bx / 24;
        int y = rest & 1, z = rest >> 1;
        int set = z >> 3, h = z & 7;
        const float* Wout = (set ? W2 : W1) + 3*DD*DD + h*DPH*DD;
        const float* V = g_v[set];
        int r0 = x * 128, n0 = y * 128;
        int tx = tid & 15, ty = tid >> 4;

        {
            int rr = tid >> 1, kq = (tid & 1) * 16;
            const float* ap = V + (size_t)(r0 + rr)*DD + h*DPH + kq;
#pragma unroll
            for (int c = 0; c < 4; c++) {
                float4 av = *(const float4*)(ap + c*4);
                sm.v.As2[kq + c*4 + 0][rr] = make_float2(av.x, av.x);
                sm.v.As2[kq + c*4 + 1][rr] = make_float2(av.y, av.y);
                sm.v.As2[kq + c*4 + 2][rr] = make_float2(av.z, av.z);
                sm.v.As2[kq + c*4 + 3][rr] = make_float2(av.w, av.w);
            }
        }
        {
            int wk = tid >> 5, wp = (tid & 31) * 2, wn = (tid & 31) * 4;
#pragma unroll
            for (int s = 0; s < 4; s++) {
                float4 wv = *(const float4*)(Wout + (size_t)(wk + 8*s)*DD + n0 + wn);
                sm.v.Ws2[wk + 8*s][wp]   = make_float2(wv.x, wv.y);
                sm.v.Ws2[wk + 8*s][wp+1] = make_float2(wv.z, wv.w);
            }
        }
        __syncthreads();

        float2 acc2[8][4];
#pragma unroll
        for (int i = 0; i < 8; i++)
#pragma unroll
            for (int j = 0; j < 4; j++) acc2[i][j] = make_float2(0.f, 0.f);

#pragma unroll
        for (int kk = 0; kk < 32; kk++) {
            float2 a[8], bfr[4];
#pragma unroll
            for (int i = 0; i < 8; i++) a[i] = sm.v.As2[kk][ty*8 + i];
#pragma unroll
            for (int j = 0; j < 4; j++) bfr[j] = sm.v.Ws2[kk][tx*4 + j];
#pragma unroll
            for (int i = 0; i < 8; i++)
#pragma unroll
                for (int j = 0; j < 4; j++) fma2(acc2[i][j], a[i], bfr[j]);
        }

#pragma unroll
        for (int i = 0; i < 8; i++) {
            int row = r0 + ty*8 + i;
            float* op = g_voh[set] + ((size_t)row*HH + h)*DD + n0 + tx*8;
            float4 o0, o1;
            o0.x = acc2[i][0].x; o0.y = acc2[i][0].y; o0.z = acc2[i][1].x; o0.w = acc2[i][1].y;
            o1.x = acc2[i][2].x; o1.y = acc2[i][2].y; o1.z = acc2[i][3].x; o1.w = acc2[i][3].y;
            *(float4*)op       = o0;
            *(float4*)(op + 4) = o1;
        }
    } else {
        int id = bx - 768;
        int h = id & 7, b = (id >> 3) & 31, set = id >> 8;

        for (int i = tid; i < EE*DPH; i += 256) {
            int q = i >> 5, d = i & 31;
            sm.s.qh[d][q] = g_qp[set][(b*EE + q)*DD + h*DPH + d];
        }
        for (int i = tid; i < MM*DPH; i += 256) {
            int m = i >> 5, d = i & 31;
            sm.s.kh[d][m] = g_kp[set][(b*MM + m)*DD + h*DPH + d];
        }
        __syncthreads();

        int q0 = (tid >> 4) * 3;
        int m0 = (tid & 15) * 6;
        float acc[3][6];
#pragma unroll
        for (int i = 0; i < 3; i++)
#pragma unroll
            for (int j = 0; j < 6; j++) acc[i][j] = 0.f;

#pragma unroll 8
        for (int kk = 0; kk < DPH; kk++) {
            float qv[3], kv[6];
#pragma unroll
            for (int i = 0; i < 3; i++) qv[i] = sm.s.qh[kk][q0 + i];
#pragma unroll
            for (int j = 0; j < 6; j++) kv[j] = sm.s.kh[kk][m0 + j];
#pragma unroll
            for (int i = 0; i < 3; i++)
#pragma unroll
                for (int j = 0; j < 6; j++) acc[i][j] += qv[i] * kv[j];
        }

        const float scale = 0.17677669529663687f;
#pragma unroll
        for (int i = 0; i < 3; i++) {
            float* sp = &g_sc[set][((size_t)(b*EE + q0 + i)*HH + h)*MM + m0];
#pragma unroll
            for (int j = 0; j < 6; j++) sp[j] = acc[i][j] * scale;
        }
    }
}

// fused single-pass LayerNorm + write (x[8] at d0..d0+3, d1..d1+3)
__device__ __forceinline__ void ln_write(
    float* x, const float* ln, float* op, int d0, int d1)
{
    float sm = 0.f, s2 = 0.f;
#pragma unroll
    for (int j = 0; j < 8; j++) { sm += x[j]; s2 += x[j]*x[j]; }
#pragma unroll
    for (int o = 16; o > 0; o >>= 1) {
        sm += __shfl_xor_sync(0xffffffffu, sm, o);
        s2 += __shfl_xor_sync(0xffffffffu, s2, o);
    }
    float mu  = sm * (1.f/DD);
    float var = fmaxf(s2 * (1.f/DD) - mu*mu, 0.f);
    float rs  = rsqrtf(var + 1e-5f);

    float4 gm0 = ldg4(ln + d0),      gm1 = ldg4(ln + d1);
    float4 bt0 = ldg4(ln + DD + d0), bt1 = ldg4(ln + DD + d1);
    float4 o0, o1;
    o0.x = (x[0]-mu)*rs*gm0.x + bt0.x; o0.y = (x[1]-mu)*rs*gm0.y + bt0.y;
    o0.z = (x[2]-mu)*rs*gm0.z + bt0.z; o0.w = (x[3]-mu)*rs*gm0.w + bt0.w;
    o1.x = (x[4]-mu)*rs*gm1.x + bt1.x; o1.y = (x[5]-mu)*rs*gm1.y + bt1.y;
    o1.z = (x[6]-mu)*rs*gm1.z + bt1.z; o1.w = (x[7]-mu)*rs*gm1.w + bt1.w;
    *(float4*)(op + d0) = o0;
    *(float4*)(op + d1) = o1;
}

// ---------------- combine v6: no smem V tile, direct L1 reads, 4 blocks/SM ----------------
__shared__ int   s_ml[MAXML];
__shared__ float s_al[SCAP][QH*HH];
__shared__ float s_mx[QH*HH];
__shared__ float s_is[QH*HH];

// accumulate n mentions (alphas in s_al[0..n-1]) into acc2
__device__ __forceinline__ void accum_chunk(
    float2 acc2[3][4], const float* __restrict__ vohb,
    int base, int n, int wid, int d0, int d1)
{
    for (int i = 0; i < n; i++) {
        const float* vrow = vohb + (size_t)s_ml[base + i]*(HH*DD);
        const float* arow = s_al[i];
#pragma unroll
        for (int hq = 0; hq < 2; hq++) {
            float4 a[3];
#pragma unroll
            for (int t = 0; t < 3; t++)
                a[t] = *(const float4*)&arow[(wid + 8*t)*8 + hq*4];
#pragma unroll
            for (int hh = 0; hh < 4; hh++) {
                const float* vp = vrow + (hq*4 + hh)*DD;
                float4 v0 = ldg4(vp + d0);
                float4 v1 = ldg4(vp + d1);
                float2 v0a = make_float2(v0.x, v0.y), v0b = make_float2(v0.z, v0.w);
                float2 v1a = make_float2(v1.x, v1.y), v1b = make_float2(v1.z, v1.w);
#pragma unroll
                for (int t = 0; t < 3; t++) {
                    float av = (hh == 0) ? a[t].x : (hh == 1) ? a[t].y : (hh == 2) ? a[t].z : a[t].w;
                    float2 aa = make_float2(av, av);
                    fma2(acc2[t][0], aa, v0a);
                    fma2(acc2[t][1], aa, v0b);
                    fma2(acc2[t][2], aa, v1a);
                    fma2(acc2[t][3], aa, v1b);
                }
            }
        }
    }
}

__global__ __launch_bounds__(256, 4) void k_combine(
    const float* __restrict__ ent,
    const float* __restrict__ b1, const float* __restrict__ ln1,
    const float* __restrict__ b2, const float* __restrict__ ln2,
    float* __restrict__ out)
{
    int e = blockIdx.x, b = blockIdx.y, z = blockIdx.z;
    int set = z >> 1, half = z & 1;
    int q0 = half * QH;
    int tid = threadIdx.x, lane = tid & 31, wid = tid >> 5;

    int cnt = g_mcnt[b*EE + e];
    if (tid < MAXML) s_ml[tid] = (tid < cnt) ? g_mlist[(b*EE + e)*MAXML + tid] : 0;
    __syncthreads();

    const float* vohb = g_voh[set] + (size_t)b*MM*HH*DD;
    const float* bbp  = (set ? b2 : b1) + 3*DD;
    const float* ln   = (set ? ln2 : ln1);
    int d0 = lane*4, d1 = 128 + lane*4;
    size_t outb = ((size_t)set*BB + b) * PAIRS * DD;

    if (cnt == 1) {
        // softmax of one element == 1: out = bias + sum_h voh[m,h,:]
        const float* vrow = vohb + (size_t)s_ml[0]*(HH*DD);
        float4 bo0 = ldg4(bbp + d0), bo1 = ldg4(bbp + d1);
        float s[8];
        s[0]=bo0.x; s[1]=bo0.y; s[2]=bo0.z; s[3]=bo0.w;
        s[4]=bo1.x; s[5]=bo1.y; s[6]=bo1.z; s[7]=bo1.w;
#pragma unroll
        for (int h = 0; h < HH; h++) {
            float4 v0 = ldg4(vrow + h*DD + d0);
            float4 v1 = ldg4(vrow + h*DD + d1);
            s[0]+=v0.x; s[1]+=v0.y; s[2]+=v0.z; s[3]+=v0.w;
            s[4]+=v1.x; s[5]+=v1.y; s[6]+=v1.z; s[7]+=v1.w;
        }
#pragma unroll
        for (int t = 0; t < 3; t++) {
            int q = q0 + wid + 8*t;
            const float* er = ent + (size_t)(b*EE + q)*DD;
            float4 e0 = ldg4(er + d0), e1 = ldg4(er + d1);
            float x[8];
            x[0]=s[0]+e0.x; x[1]=s[1]+e0.y; x[2]=s[2]+e0.z; x[3]=s[3]+e0.w;
            x[4]=s[4]+e1.x; x[5]=s[5]+e1.y; x[6]=s[6]+e1.z; x[7]=s[7]+e1.w;
            int orow = set ? (q*EE + e) : (e*EE + q);
            ln_write(x, ln, out + outb + (size_t)orow*DD, d0, d1);
        }
        return;
    }

    const float* scb = g_sc[set] + (size_t)b*EE*HH*MM;

    float2 acc2[3][4];
#pragma unroll
    for (int t = 0; t < 3; t++)
#pragma unroll
        for (int j = 0; j < 4; j++) acc2[t][j] = make_float2(0.f, 0.f);

    if (cnt <= SCAP) {
        // one (lq,h) task per thread; exp once, rescale in place
        if (tid < QH*HH) {
            int lq = tid >> 3, h = tid & 7;
            const float* sp = scb + ((size_t)(q0 + lq)*HH + h)*MM;
            float sv[SCAP];
            float mx = -1e30f;
            for (int i = 0; i < cnt; i++) { sv[i] = sp[s_ml[i]]; mx = fmaxf(mx, sv[i]); }
            float s = 0.f;
            for (int i = 0; i < cnt; i++) { sv[i] = __expf(sv[i] - mx); s += sv[i]; }
            float inv = 1.f / s;
            for (int i = 0; i < cnt; i++) s_al[i][tid] = sv[i] * inv;
        }
        __syncthreads();
        accum_chunk(acc2, vohb, 0, cnt, wid, d0, d1);
    } else {
        // rare: global max/sum first, then chunks of SCAP
        for (int t = tid; t < QH*HH; t += 256) {
            int lq = t >> 3, h = t & 7;
            const float* sp = scb + ((size_t)(q0 + lq)*HH + h)*MM;
            float mx = -1e30f;
            for (int i = 0; i < cnt; i++) mx = fmaxf(mx, sp[s_ml[i]]);
            float s = 0.f;
            for (int i = 0; i < cnt; i++) s += __expf(sp[s_ml[i]] - mx);
            s_mx[t] = mx; s_is[t] = 1.f / s;
        }
        __syncthreads();
        for (int base = 0; base < cnt; base += SCAP) {
            int n = min(SCAP, cnt - base);
            for (int idx = tid; idx < QH*HH*n; idx += 256) {
                int i = idx / (QH*HH), t = idx - i*(QH*HH);
                int lq = t >> 3, h = t & 7;
                float sv = scb[((size_t)(q0 + lq)*HH + h)*MM + s_ml[base + i]];
                s_al[i][t] = __expf(sv - s_mx[t]) * s_is[t];
            }
            __syncthreads();
            accum_chunk(acc2, vohb, base, n, wid, d0, d1);
            __syncthreads();
        }
    }

    float4 bo0 = ldg4(bbp + d0), bo1 = ldg4(bbp + d1);
#pragma unroll
    for (int t = 0; t < 3; t++) {
        int q = q0 + wid + 8*t;
        const float* er = ent + (size_t)(b*EE + q)*DD;
        float4 e0 = ldg4(er + d0), e1 = ldg4(er + d1);
        float x[8];
        x[0] = acc2[t][0].x + bo0.x + e0.x; x[1] = acc2[t][0].y + bo0.y + e0.y;
        x[2] = acc2[t][1].x + bo0.z + e0.z; x[3] = acc2[t][1].y + bo0.w + e0.w;
        x[4] = acc2[t][2].x + bo1.x + e1.x; x[5] = acc2[t][2].y + bo1.y + e1.y;
        x[6] = acc2[t][3].x + bo1.z + e1.z; x[7] = acc2[t][3].y + bo1.w + e1.w;
        int orow = set ? (q*EE + e) : (e*EE + q);
        ln_write(x, ln, out + outb + (size_t)orow*DD, d0, d1);
    }
}

// ---------------- launch ----------------
extern "C" void kernel_launch(void* const* d_in, const int* in_sizes, int n_in,
                              void* d_out, int out_size) {
    const void*  info = d_in[0];
    const float* ent  = (const float*)d_in[2];
    const float* men  = (const float*)d_in[3];
    const float* sen  = (const float*)d_in[4];
    const float* W1   = (const float*)d_in[5];
    const float* b1   = (const float*)d_in[6];
    const float* ln1  = (const float*)d_in[7];
    const float* W2   = (const float*)d_in[8];
    const float* b2   = (const float*)d_in[9];
    const float* ln2  = (const float*)d_in[10];
    float* out = (float*)d_out;

    k_prep<<<BB, 128>>>(info);
    k_proj_all<<<240, 256>>>(ent, men, sen, W1, b1, W2, b2);
    k_vs<<<1280, 256>>>(W1, W2);
    k_combine<<<dim3(EE, BB, 4), 256>>>(ent, b1, ln1, b2, ln2, out);
}